// round 5
// baseline (speedup 1.0000x reference)
#include <cuda_runtime.h>
#include <mma.h>
#include <math.h>
using namespace nvcuda;

// ---------------------------------------------------------------------------
// Problem constants
// ---------------------------------------------------------------------------
#define TTS   21      // Tm = CAP-1 decode steps
#define CAPL  22
#define BBS   128     // batch
#define PPS   196     // pixels
#define ENCD  2048
#define DHID  1024
#define VOC   32000

static constexpr long long O_PRED = 0;
static constexpr long long O_CAPS = (long long)BBS * TTS * VOC;   // 86,016,000
static constexpr long long O_DECL = O_CAPS + (long long)BBS * CAPL;
static constexpr long long O_SORT = O_DECL + BBS;
static constexpr long long O_RPOS = O_SORT + BBS;
static constexpr long long O_PPOS = O_RPOS + (long long)BBS * TTS;

// ---------------------------------------------------------------------------
// Static device scratch (no runtime allocation allowed)
// ---------------------------------------------------------------------------
__device__ float d_encs [(size_t)BBS * PPS * ENCD];   // sorted encoder (205.5 MB)
__device__ float d_att1 [(size_t)BBS * PPS * DHID];   // att1 (102.8 MB)
__device__ float d_econ [(size_t)TTS * BBS * 4 * DHID]; // embed @ Wih_e^T (44 MB)
__device__ float d_embg [(size_t)TTS * BBS * DHID];   // gathered embeddings
__device__ float d_W1cat[4096 * 2048];                // [Wih(:,1024:2048) | Whh]
__device__ float d_W2cat[(size_t)4096 * 4096];        // [l2_Wih | l2_Whh]
__device__ float d_W3cat[3072 * 1024];                // [dec_att_W ; f_beta_W]
__device__ float d_b1sum[4096];
__device__ float d_b2sum[4096];
__device__ float d_b3cat[3072];
__device__ float d_base1[BBS * 4096];                 // biases + mean_enc contrib
__device__ float d_gates[BBS * 4096];
__device__ float d_x1   [BBS * 2048];                 // [h2_state | h1_state]
__device__ float d_x2   [BBS * 4096];                 // [att | h1n | h2_state]
__device__ float d_ag   [BBS * 3072];                 // [att2 | gate logits]
__device__ float d_c1   [BBS * DHID];
__device__ float d_c2   [BBS * DHID];
__device__ float d_mean [BBS * ENCD];
__device__ float d_h2all[(size_t)TTS * BBS * DHID];   // unmasked h2n candidates
__device__ int   d_sort  [BBS];
__device__ int   d_declen[BBS];
__device__ int   d_tokens[TTS * BBS];

// ---------------------------------------------------------------------------
// Math helpers
// ---------------------------------------------------------------------------
__device__ __forceinline__ float sigf(float x) {
    return 1.0f / (1.0f + __expf(-x));
}
__device__ __forceinline__ float tanh_fast(float x) {
    return 1.0f - 2.0f / (__expf(2.0f * x) + 1.0f);
}
__device__ __forceinline__ float tf32r(float x) {
    float r;
    asm("cvt.rna.tf32.f32 %0, %1;" : "=f"(r) : "f"(x));
    return r;
}

// ---------------------------------------------------------------------------
// Setup: stable descending argsort of lengths; caps/dec_len/sort/rel_pos out
// ---------------------------------------------------------------------------
__global__ void setup_kernel(const int* __restrict__ caplen,
                             const int* __restrict__ caps,
                             float* __restrict__ out) {
    __shared__ int lens_s[BBS];
    __shared__ int sort_s[BBS];
    int i = threadIdx.x;
    int li = caplen[i];
    lens_s[i] = li;
    __syncthreads();
    int rank = 0;
    for (int j = 0; j < BBS; ++j) {
        int lj = lens_s[j];
        if (lj > li || (lj == li && j < i)) rank++;
    }
    sort_s[rank] = i;
    __syncthreads();
    int src = sort_s[i];
    d_sort[i] = src;
    int dl = lens_s[src] - 1;
    d_declen[i] = dl;
    out[O_DECL + i] = (float)dl;
    out[O_SORT + i] = (float)src;
    for (int t = 0; t < CAPL; ++t) {
        int tok = caps[src * CAPL + t];
        out[O_CAPS + (long long)i * CAPL + t] = (float)tok;
        if (t < TTS) d_tokens[t * BBS + i] = tok;
    }
    float dlf = (float)dl;
    for (int s = 0; s < TTS; ++s)
        out[O_RPOS + (long long)i * TTS + s] =
            (s < dl) ? ((float)(s + 1) / dlf) : 0.0f;
}

// ---------------------------------------------------------------------------
// Gather sorted encoder rows (float4), 50176 blocks x 256
// ---------------------------------------------------------------------------
__global__ void gather_enc_kernel(const float* __restrict__ enc) {
    int g = blockIdx.x * 256 + threadIdx.x;          // float4 index
    const int V4ROW = ENCD / 4;                      // 512
    int r = g / V4ROW;                               // sorted row 0..25087
    int w = g % V4ROW;
    int b = r / PPS, p = r % PPS;
    int srow = d_sort[b] * PPS + p;
    const float4* src = (const float4*)enc;
    float4* dst = (float4*)d_encs;
    dst[(size_t)r * V4ROW + w] = src[(size_t)srow * V4ROW + w];
}

// ---------------------------------------------------------------------------
// mean over pixels: one thread per (b,e)
// ---------------------------------------------------------------------------
__global__ void mean_kernel() {
    int idx = blockIdx.x * 256 + threadIdx.x;        // 0 .. 128*2048
    int b = idx / ENCD, e = idx % ENCD;
    const float* base = d_encs + (size_t)b * PPS * ENCD + e;
    float s = 0.f;
    #pragma unroll 4
    for (int p = 0; p < PPS; ++p) s += base[(size_t)p * ENCD];
    d_mean[idx] = s * (1.0f / (float)PPS);
}

// ---------------------------------------------------------------------------
// Weight concatenation copies (float4) + bias sums
// ---------------------------------------------------------------------------
__global__ void w1copy_kernel(const float* __restrict__ l1Wih,
                              const float* __restrict__ l1Whh) {
    int g = blockIdx.x * 256 + threadIdx.x;          // float4 over 4096x2048
    int j = g / (2048 / 4);
    int c = (g % (2048 / 4)) * 4;
    float4 v;
    if (c < 1024) v = *(const float4*)(l1Wih + (size_t)j * 4096 + 1024 + c);
    else          v = *(const float4*)(l1Whh + (size_t)j * 1024 + (c - 1024));
    *(float4*)(d_W1cat + (size_t)j * 2048 + c) = v;
}

__global__ void w2copy_kernel(const float* __restrict__ l2Wih,
                              const float* __restrict__ l2Whh) {
    int g = blockIdx.x * 256 + threadIdx.x;          // float4 over 4096x4096
    int j = g / (4096 / 4);
    int c = (g % (4096 / 4)) * 4;
    float4 v;
    if (c < 3072) v = *(const float4*)(l2Wih + (size_t)j * 3072 + c);
    else          v = *(const float4*)(l2Whh + (size_t)j * 1024 + (c - 3072));
    *(float4*)(d_W2cat + (size_t)j * 4096 + c) = v;
}

__global__ void w3copy_kernel(const float* __restrict__ daW,
                              const float* __restrict__ fbW) {
    int g = blockIdx.x * 256 + threadIdx.x;          // float4 over 3072x1024
    int j = g / (1024 / 4);
    int c = (g % (1024 / 4)) * 4;
    float4 v;
    if (j < 1024) v = *(const float4*)(daW + (size_t)j * 1024 + c);
    else          v = *(const float4*)(fbW + (size_t)(j - 1024) * 1024 + c);
    *(float4*)(d_W3cat + (size_t)j * 1024 + c) = v;
}

__global__ void bias_kernel(const float* __restrict__ l1bih,
                            const float* __restrict__ l1bhh,
                            const float* __restrict__ l2bih,
                            const float* __restrict__ l2bhh,
                            const float* __restrict__ dab,
                            const float* __restrict__ fbb) {
    int j = blockIdx.x * 256 + threadIdx.x;          // 0..4095
    d_b1sum[j] = l1bih[j] + l1bhh[j];
    d_b2sum[j] = l2bih[j] + l2bhh[j];
    if (j < 3072) d_b3cat[j] = (j < 1024) ? dab[j] : fbb[j - 1024];
}

// ---------------------------------------------------------------------------
// Gather token embeddings: one block per row (t*128+b)
// ---------------------------------------------------------------------------
__global__ void embg_kernel(const float* __restrict__ emb) {
    int m = blockIdx.x;
    int tok = d_tokens[m];
    const float4* src = (const float4*)(emb + (size_t)tok * DHID);
    float4* dst = (float4*)(d_embg + (size_t)m * DHID);
    dst[threadIdx.x] = src[threadIdx.x];
}

// ---------------------------------------------------------------------------
// Zero initial states
// ---------------------------------------------------------------------------
__global__ void zero_kernel() {
    int idx = blockIdx.x * 256 + threadIdx.x;        // 0 .. 524287
    d_x2[idx] = 0.f;
    if (idx < BBS * 2048) d_x1[idx] = 0.f;
    if (idx < BBS * DHID) { d_c1[idx] = 0.f; d_c2[idx] = 0.f; }
}

// ---------------------------------------------------------------------------
// TF32x3 tensor-core GEMM: C[m,n] = sum_k A[m,k]*B[n,k] (+bias) (+adds)
// A split into hi/lo tf32 parts; 3 MMAs give ~fp32 accuracy at tensor speed.
// BM x BN block tile, BK=16, warp tile WM x WN (m16n16k8 wmma fragments).
// PRED variant: permuted masked store into the predictions output.
// All M,N,K at call sites are multiples of BM/BN/BK respectively.
// ---------------------------------------------------------------------------
template<int BM, int BN, int WM, int WN, bool BIAS, int NADD, bool PRED>
__global__ void gemm_tf32(const float* __restrict__ A,
                          const float* __restrict__ Bm,
                          const float* __restrict__ bias,
                          const float* __restrict__ add0,
                          const float* __restrict__ add1,
                          float* __restrict__ C,
                          int N, int K, int lda, int ldb, int ldc) {
    constexpr int BK = 16;
    constexpr int LDT = BK + 8;                      // 24: pad, 16B-multiple
    constexpr int WARPS_M = BM / WM;
    constexpr int WARPS_N = BN / WN;
    constexpr int NTH = WARPS_M * WARPS_N * 32;
    constexpr int MFR = WM / 16;
    constexpr int NFR = WN / 16;
    constexpr int SM_A = BM * LDT;
    constexpr int SM_B = BN * LDT;
    constexpr int SMEMF = (2 * SM_A + 2 * SM_B) > (BM * BN)
                        ? (2 * SM_A + 2 * SM_B) : (BM * BN);
    __shared__ float smem[SMEMF];
    float* Ah = smem;
    float* Al = smem + SM_A;
    float* Bh = smem + 2 * SM_A;
    float* Bl = smem + 2 * SM_A + SM_B;

    const int tid  = threadIdx.x;
    const int warp = tid >> 5;
    const int wm = (warp / WARPS_N) * WM;
    const int wn = (warp % WARPS_N) * WN;
    const int m0 = blockIdx.y * BM;
    const int n0 = blockIdx.x * BN;

    wmma::fragment<wmma::accumulator, 16, 16, 8, float> cf[MFR][NFR];
    #pragma unroll
    for (int i = 0; i < MFR; ++i)
        #pragma unroll
        for (int j = 0; j < NFR; ++j)
            wmma::fill_fragment(cf[i][j], 0.0f);

    for (int k0 = 0; k0 < K; k0 += BK) {
        // cooperative hi/lo split load of A tile
        #pragma unroll
        for (int i = tid; i < BM * BK / 4; i += NTH) {
            int m  = i / (BK / 4);
            int kq = (i % (BK / 4)) * 4;
            float4 v = *(const float4*)(A + (size_t)(m0 + m) * lda + k0 + kq);
            float h0 = tf32r(v.x), h1 = tf32r(v.y), h2 = tf32r(v.z), h3 = tf32r(v.w);
            float* ph = Ah + m * LDT + kq;
            float* pl = Al + m * LDT + kq;
            ph[0] = h0; ph[1] = h1; ph[2] = h2; ph[3] = h3;
            pl[0] = tf32r(v.x - h0); pl[1] = tf32r(v.y - h1);
            pl[2] = tf32r(v.z - h2); pl[3] = tf32r(v.w - h3);
        }
        // cooperative hi/lo split load of B tile
        #pragma unroll
        for (int i = tid; i < BN * BK / 4; i += NTH) {
            int n  = i / (BK / 4);
            int kq = (i % (BK / 4)) * 4;
            float4 v = *(const float4*)(Bm + (size_t)(n0 + n) * ldb + k0 + kq);
            float h0 = tf32r(v.x), h1 = tf32r(v.y), h2 = tf32r(v.z), h3 = tf32r(v.w);
            float* ph = Bh + n * LDT + kq;
            float* pl = Bl + n * LDT + kq;
            ph[0] = h0; ph[1] = h1; ph[2] = h2; ph[3] = h3;
            pl[0] = tf32r(v.x - h0); pl[1] = tf32r(v.y - h1);
            pl[2] = tf32r(v.z - h2); pl[3] = tf32r(v.w - h3);
        }
        __syncthreads();

        #pragma unroll
        for (int kk = 0; kk < BK; kk += 8) {
            wmma::fragment<wmma::matrix_a, 16, 16, 8, wmma::precision::tf32,
                           wmma::row_major> ah[MFR], al[MFR];
            wmma::fragment<wmma::matrix_b, 16, 16, 8, wmma::precision::tf32,
                           wmma::col_major> bh[NFR], bl[NFR];
            #pragma unroll
            for (int i = 0; i < MFR; ++i) {
                wmma::load_matrix_sync(ah[i], Ah + (wm + i * 16) * LDT + kk, LDT);
                wmma::load_matrix_sync(al[i], Al + (wm + i * 16) * LDT + kk, LDT);
            }
            #pragma unroll
            for (int j = 0; j < NFR; ++j) {
                wmma::load_matrix_sync(bh[j], Bh + (wn + j * 16) * LDT + kk, LDT);
                wmma::load_matrix_sync(bl[j], Bl + (wn + j * 16) * LDT + kk, LDT);
            }
            #pragma unroll
            for (int i = 0; i < MFR; ++i)
                #pragma unroll
                for (int j = 0; j < NFR; ++j) {
                    wmma::mma_sync(cf[i][j], ah[i], bh[j], cf[i][j]);
                    wmma::mma_sync(cf[i][j], al[i], bh[j], cf[i][j]);
                    wmma::mma_sync(cf[i][j], ah[i], bl[j], cf[i][j]);
                }
        }
        __syncthreads();
    }

    // stage results through shared (aliases tile buffers; all MMAs done)
    float* outs = smem;
    #pragma unroll
    for (int i = 0; i < MFR; ++i)
        #pragma unroll
        for (int j = 0; j < NFR; ++j)
            wmma::store_matrix_sync(outs + (wm + i * 16) * BN + (wn + j * 16),
                                    cf[i][j], BN, wmma::mem_row_major);
    __syncthreads();

    for (int i = tid; i < BM * BN; i += NTH) {
        int m = i / BN, n = i % BN;
        float v = outs[i];
        int gm = m0 + m, gn = n0 + n;
        if (BIAS)      v += bias[gn];
        if (NADD >= 1) v += add0[(size_t)gm * ldc + gn];
        if (NADD >= 2) v += add1[(size_t)gm * ldc + gn];
        if (PRED) {
            int t = gm / BBS, b = gm % BBS;
            C[(long long)(b * TTS + t) * N + gn] = (t < d_declen[b]) ? v : 0.f;
        } else {
            C[(size_t)gm * ldc + gn] = v;
        }
    }
}

// ---------------------------------------------------------------------------
// LSTM pointwise kernels (gate order: i, f, g, o)
// ---------------------------------------------------------------------------
__global__ void lstm1_kernel(int t) {
    int idx = blockIdx.x * 256 + threadIdx.x;        // 0 .. 128*1024
    int b = idx / DHID, k = idx % DHID;
    const float* g = d_gates + (size_t)b * 4096;
    float ig = g[k], fg = g[1024 + k], gg = g[2048 + k], og = g[3072 + k];
    float c = d_c1[idx];
    float cn = sigf(fg) * c + sigf(ig) * tanhf(gg);
    float hn = sigf(og) * tanhf(cn);
    d_x2[(size_t)b * 4096 + 2048 + k] = hn;          // candidate h1n (unmasked)
    if (t < d_declen[b]) {
        d_c1[idx] = cn;
        d_x1[(size_t)b * 2048 + 1024 + k] = hn;      // carried h1 state
    }
}

__global__ void lstm2_kernel(int t) {
    int idx = blockIdx.x * 256 + threadIdx.x;
    int b = idx / DHID, k = idx % DHID;
    const float* g = d_gates + (size_t)b * 4096;
    float ig = g[k], fg = g[1024 + k], gg = g[2048 + k], og = g[3072 + k];
    float c = d_c2[idx];
    float cn = sigf(fg) * c + sigf(ig) * tanhf(gg);
    float hn = sigf(og) * tanhf(cn);
    d_h2all[(size_t)(t * BBS + b) * DHID + k] = hn;  // candidate (unmasked)
    if (t < d_declen[b]) {
        d_c2[idx] = cn;
        d_x1[(size_t)b * 2048 + k] = hn;             // carried h2 state
        d_x2[(size_t)b * 4096 + 3072 + k] = hn;
    }
}

// ---------------------------------------------------------------------------
// Fused attention: scores = tanh(att1 + att2) . w + b0; softmax over p;
// awe = alpha @ enc; x2.att = sigmoid(gate_logits) * awe.   One block per b.
// ---------------------------------------------------------------------------
__global__ void attn_kernel(const float* __restrict__ fullW,
                            const float* __restrict__ fullb) {
    __shared__ float s_a2[DHID];
    __shared__ float s_w [DHID];
    __shared__ float s_sc[PPS];
    __shared__ float s_red[256];
    const int b = blockIdx.x;
    const int tid = threadIdx.x;
    const int lane = tid & 31, warp = tid >> 5;

    for (int i = tid; i < DHID; i += 256) {
        s_a2[i] = d_ag[(size_t)b * 3072 + i];
        s_w[i]  = fullW[i];
    }
    __syncthreads();

    const float b0 = fullb[0];
    for (int p = warp; p < PPS; p += 8) {
        const float* row = d_att1 + ((size_t)b * PPS + p) * DHID;
        float s = 0.f;
        #pragma unroll 8
        for (int a = lane; a < DHID; a += 32)
            s += tanh_fast(row[a] + s_a2[a]) * s_w[a];
        #pragma unroll
        for (int o = 16; o > 0; o >>= 1)
            s += __shfl_down_sync(0xffffffffu, s, o);
        if (lane == 0) s_sc[p] = s + b0;
    }
    __syncthreads();

    // softmax over 196
    s_red[tid] = (tid < PPS) ? s_sc[tid] : -INFINITY;
    __syncthreads();
    for (int s = 128; s > 0; s >>= 1) {
        if (tid < s) s_red[tid] = fmaxf(s_red[tid], s_red[tid + s]);
        __syncthreads();
    }
    float mx = s_red[0];
    __syncthreads();
    float e = 0.f;
    if (tid < PPS) { e = __expf(s_sc[tid] - mx); }
    s_red[tid] = e;
    __syncthreads();
    for (int s = 128; s > 0; s >>= 1) {
        if (tid < s) s_red[tid] += s_red[tid + s];
        __syncthreads();
    }
    float inv = 1.0f / s_red[0];
    __syncthreads();
    if (tid < PPS) s_sc[tid] = e * inv;              // alpha
    __syncthreads();

    // awe + gate
    const float* encb = d_encs + (size_t)b * PPS * ENCD;
    for (int ei = tid; ei < ENCD; ei += 256) {
        float acc = 0.f;
        const float* col = encb + ei;
        #pragma unroll 4
        for (int p = 0; p < PPS; ++p)
            acc = fmaf(s_sc[p], col[(size_t)p * ENCD], acc);
        float gate = sigf(d_ag[(size_t)b * 3072 + 1024 + ei]);
        d_x2[(size_t)b * 4096 + ei] = gate * acc;
    }
}

// ---------------------------------------------------------------------------
// predicted_pos: one warp per (t,b) row
// ---------------------------------------------------------------------------
__global__ void rpm_kernel(const float* __restrict__ rpmW,
                           float* __restrict__ out) {
    int m = blockIdx.x * 8 + (threadIdx.x >> 5);
    if (m >= TTS * BBS) return;
    int lane = threadIdx.x & 31;
    int t = m / BBS, b = m % BBS;
    const float* h = d_h2all + (size_t)m * DHID;
    float s = 0.f;
    #pragma unroll 8
    for (int k = lane; k < DHID; k += 32) s += h[k] * rpmW[k];
    #pragma unroll
    for (int o = 16; o > 0; o >>= 1)
        s += __shfl_down_sync(0xffffffffu, s, o);
    if (lane == 0)
        out[O_PPOS + (long long)b * TTS + t] =
            (t < d_declen[b]) ? sigf(s) : 0.f;
}

// ---------------------------------------------------------------------------
// Launch
// ---------------------------------------------------------------------------
extern "C" void kernel_launch(void* const* d_in, const int* in_sizes, int n_in,
                              void* d_out, int out_size) {
    const float* enc_out = (const float*)d_in[0];
    const int*   caps    = (const int*)  d_in[1];
    const int*   caplen  = (const int*)  d_in[2];
    const float* emb     = (const float*)d_in[3];
    const float* eaW     = (const float*)d_in[4];
    const float* eab     = (const float*)d_in[5];
    const float* daW     = (const float*)d_in[6];
    const float* dab     = (const float*)d_in[7];
    const float* faW     = (const float*)d_in[8];
    const float* fab     = (const float*)d_in[9];
    const float* fbW     = (const float*)d_in[10];
    const float* fbb     = (const float*)d_in[11];
    const float* l1Wih   = (const float*)d_in[12];
    const float* l1Whh   = (const float*)d_in[13];
    const float* l1bih   = (const float*)d_in[14];
    const float* l1bhh   = (const float*)d_in[15];
    const float* l2Wih   = (const float*)d_in[16];
    const float* l2Whh   = (const float*)d_in[17];
    const float* l2bih   = (const float*)d_in[18];
    const float* l2bhh   = (const float*)d_in[19];
    const float* ramW    = (const float*)d_in[20];
    const float* ramb    = (const float*)d_in[21];
    const float* rpmW    = (const float*)d_in[22];
    float* out = (float*)d_out;

    float* p_encs;  cudaGetSymbolAddress((void**)&p_encs,  d_encs);
    float* p_att1;  cudaGetSymbolAddress((void**)&p_att1,  d_att1);
    float* p_econ;  cudaGetSymbolAddress((void**)&p_econ,  d_econ);
    float* p_embg;  cudaGetSymbolAddress((void**)&p_embg,  d_embg);
    float* p_W1;    cudaGetSymbolAddress((void**)&p_W1,    d_W1cat);
    float* p_W2;    cudaGetSymbolAddress((void**)&p_W2,    d_W2cat);
    float* p_W3;    cudaGetSymbolAddress((void**)&p_W3,    d_W3cat);
    float* p_b1;    cudaGetSymbolAddress((void**)&p_b1,    d_b1sum);
    float* p_b2;    cudaGetSymbolAddress((void**)&p_b2,    d_b2sum);
    float* p_b3;    cudaGetSymbolAddress((void**)&p_b3,    d_b3cat);
    float* p_base1; cudaGetSymbolAddress((void**)&p_base1, d_base1);
    float* p_gates; cudaGetSymbolAddress((void**)&p_gates, d_gates);
    float* p_x1;    cudaGetSymbolAddress((void**)&p_x1,    d_x1);
    float* p_x2;    cudaGetSymbolAddress((void**)&p_x2,    d_x2);
    float* p_ag;    cudaGetSymbolAddress((void**)&p_ag,    d_ag);
    float* p_mean;  cudaGetSymbolAddress((void**)&p_mean,  d_mean);
    float* p_h2;    cudaGetSymbolAddress((void**)&p_h2,    d_h2all);

    // 1. sort / small outputs / tokens
    setup_kernel<<<1, BBS>>>(caplen, caps, out);

    // 2. gather sorted encoder
    gather_enc_kernel<<<50176, 256>>>(enc_out);

    // 3. mean over pixels
    mean_kernel<<<(BBS * ENCD) / 256, 256>>>();

    // 4. weight concatenations + bias sums
    bias_kernel<<<4096 / 256, 256>>>(l1bih, l1bhh, l2bih, l2bhh, dab, fbb);
    w1copy_kernel<<<(4096 * 2048 / 4) / 256, 256>>>(l1Wih, l1Whh);
    w2copy_kernel<<<(4096 * 4096 / 4) / 256, 256>>>(l2Wih, l2Whh);
    w3copy_kernel<<<(3072 * 1024 / 4) / 256, 256>>>(daW, fbW);

    // 5. token embedding gather
    embg_kernel<<<TTS * BBS, 256>>>(emb);

    // 6. base1 = mean_enc @ Wih[:,2048:].T + (bih+bhh)   (128 x 4096, K=2048)
    gemm_tf32<64, 64, 32, 32, true, 0, false><<<dim3(4096 / 64, 2), 128>>>(
        p_mean, l1Wih + 2048, p_b1, nullptr, nullptr, p_base1,
        4096, 2048, 2048, 4096, 4096);

    // 7. econ = embg @ Wih[:,0:1024].T   (2688 x 4096, K=1024)
    gemm_tf32<128, 64, 32, 32, false, 0, false><<<dim3(4096 / 64, 21), 256>>>(
        p_embg, l1Wih, nullptr, nullptr, nullptr, p_econ,
        4096, 1024, 1024, 4096, 4096);

    // 8. att1 = enc_sorted @ enc_att_W.T + b   (25088 x 1024, K=2048)
    gemm_tf32<128, 64, 32, 32, true, 0, false><<<dim3(1024 / 64, 196), 256>>>(
        p_encs, eaW, eab, nullptr, nullptr, p_att1,
        1024, 2048, 2048, 2048, 1024);

    // 9. zero states
    zero_kernel<<<(BBS * 4096) / 256, 256>>>();

    // 10. sequential decode
    for (int t = 0; t < TTS; ++t) {
        // gates1 = [h2|h1] @ W1cat.T + base1 + econ[t]
        gemm_tf32<64, 64, 32, 32, false, 2, false><<<dim3(4096 / 64, 2), 128>>>(
            p_x1, p_W1, nullptr, p_base1, p_econ + (size_t)t * BBS * 4096,
            p_gates, 4096, 2048, 2048, 2048, 4096);

        lstm1_kernel<<<(BBS * DHID) / 256, 256>>>(t);

        // [att2 | gate logits] = h1n @ [dec_att_W ; f_beta_W].T + b3
        gemm_tf32<64, 64, 32, 32, true, 0, false><<<dim3(3072 / 64, 2), 128>>>(
            p_x2 + 2048, p_W3, p_b3, nullptr, nullptr, p_ag,
            3072, 1024, 4096, 1024, 3072);

        attn_kernel<<<BBS, 256>>>(faW, fab);

        // gates2 = [att|h1n|h2] @ [l2_Wih|l2_Whh].T + (bih+bhh)
        gemm_tf32<64, 64, 32, 32, true, 0, false><<<dim3(4096 / 64, 2), 128>>>(
            p_x2, p_W2, p_b2, nullptr, nullptr, p_gates,
            4096, 4096, 4096, 4096, 4096);

        lstm2_kernel<<<(BBS * DHID) / 256, 256>>>(t);
    }

    // 11. predictions = h2all @ ram_W.T + ram_b, permuted + masked store
    gemm_tf32<128, 64, 32, 32, true, 0, true><<<dim3(VOC / 64, 21), 256>>>(
        p_h2, ramW, ramb, nullptr, nullptr, out + O_PRED,
        VOC, 1024, 1024, 1024, VOC);

    // 12. predicted_pos
    rpm_kernel<<<(TTS * BBS + 7) / 8, 256>>>(rpmW, out);
}

// round 6
// speedup vs baseline: 1.0114x; 1.0114x over previous
#include <cuda_runtime.h>
#include <mma.h>
#include <math.h>
using namespace nvcuda;

// ---------------------------------------------------------------------------
// Problem constants
// ---------------------------------------------------------------------------
#define TTS   21      // Tm = CAP-1 decode steps
#define CAPL  22
#define BBS   128     // batch
#define PPS   196     // pixels
#define ENCD  2048
#define DHID  1024
#define VOC   32000

static constexpr long long O_PRED = 0;
static constexpr long long O_CAPS = (long long)BBS * TTS * VOC;   // 86,016,000
static constexpr long long O_DECL = O_CAPS + (long long)BBS * CAPL;
static constexpr long long O_SORT = O_DECL + BBS;
static constexpr long long O_RPOS = O_SORT + BBS;
static constexpr long long O_PPOS = O_RPOS + (long long)BBS * TTS;

// ---------------------------------------------------------------------------
// Static device scratch (no runtime allocation allowed)
// ---------------------------------------------------------------------------
__device__ float d_encs [(size_t)BBS * PPS * ENCD];   // sorted encoder (205.5 MB)
__device__ float d_att1 [(size_t)BBS * PPS * DHID];   // att1 (102.8 MB)
__device__ float d_econ [(size_t)TTS * BBS * 4 * DHID]; // embed @ Wih_e^T (44 MB)
__device__ float d_embg [(size_t)TTS * BBS * DHID];   // gathered embeddings
__device__ float d_W1cat[4096 * 2048];                // [Wih(:,1024:2048) | Whh]
__device__ float d_W2cat[(size_t)4096 * 4096];        // [l2_Wih | l2_Whh]
__device__ float d_W3cat[3072 * 1024];                // [dec_att_W ; f_beta_W]
__device__ float d_b1sum[4096];
__device__ float d_b2sum[4096];
__device__ float d_b3cat[3072];
__device__ float d_base1[BBS * 4096];                 // biases + mean_enc contrib
__device__ float d_gates[BBS * 4096];
__device__ float d_x1   [BBS * 2048];                 // [h2_state | h1_state]
__device__ float d_x2   [BBS * 4096];                 // [att | h1n | h2_state]
__device__ float d_ag   [BBS * 3072];                 // [att2 | gate logits]
__device__ float d_c1   [BBS * DHID];
__device__ float d_c2   [BBS * DHID];
__device__ float d_mean [BBS * ENCD];
__device__ float d_h2all[(size_t)TTS * BBS * DHID];   // unmasked h2n candidates
__device__ int   d_sort  [BBS];
__device__ int   d_declen[BBS];
__device__ int   d_tokens[TTS * BBS];

// ---------------------------------------------------------------------------
// Math helpers
// ---------------------------------------------------------------------------
__device__ __forceinline__ float sigf(float x) {
    return 1.0f / (1.0f + __expf(-x));
}
__device__ __forceinline__ float tanh_fast(float x) {
    return 1.0f - 2.0f / (__expf(2.0f * x) + 1.0f);
}
__device__ __forceinline__ float tf32r(float x) {
    float r;
    asm("cvt.rna.tf32.f32 %0, %1;" : "=f"(r) : "f"(x));
    return r;
}

// ---------------------------------------------------------------------------
// Setup: stable descending argsort of lengths; caps/dec_len/sort/rel_pos out
// ---------------------------------------------------------------------------
__global__ void setup_kernel(const int* __restrict__ caplen,
                             const int* __restrict__ caps,
                             float* __restrict__ out) {
    __shared__ int lens_s[BBS];
    __shared__ int sort_s[BBS];
    int i = threadIdx.x;
    int li = caplen[i];
    lens_s[i] = li;
    __syncthreads();
    int rank = 0;
    for (int j = 0; j < BBS; ++j) {
        int lj = lens_s[j];
        if (lj > li || (lj == li && j < i)) rank++;
    }
    sort_s[rank] = i;
    __syncthreads();
    int src = sort_s[i];
    d_sort[i] = src;
    int dl = lens_s[src] - 1;
    d_declen[i] = dl;
    out[O_DECL + i] = (float)dl;
    out[O_SORT + i] = (float)src;
    for (int t = 0; t < CAPL; ++t) {
        int tok = caps[src * CAPL + t];
        out[O_CAPS + (long long)i * CAPL + t] = (float)tok;
        if (t < TTS) d_tokens[t * BBS + i] = tok;
    }
    float dlf = (float)dl;
    for (int s = 0; s < TTS; ++s)
        out[O_RPOS + (long long)i * TTS + s] =
            (s < dl) ? ((float)(s + 1) / dlf) : 0.0f;
}

// ---------------------------------------------------------------------------
// Gather sorted encoder rows (float4), 50176 blocks x 256
// ---------------------------------------------------------------------------
__global__ void gather_enc_kernel(const float* __restrict__ enc) {
    int g = blockIdx.x * 256 + threadIdx.x;          // float4 index
    const int V4ROW = ENCD / 4;                      // 512
    int r = g / V4ROW;                               // sorted row 0..25087
    int w = g % V4ROW;
    int b = r / PPS, p = r % PPS;
    int srow = d_sort[b] * PPS + p;
    const float4* src = (const float4*)enc;
    float4* dst = (float4*)d_encs;
    dst[(size_t)r * V4ROW + w] = src[(size_t)srow * V4ROW + w];
}

// ---------------------------------------------------------------------------
// mean over pixels: one thread per (b,e)
// ---------------------------------------------------------------------------
__global__ void mean_kernel() {
    int idx = blockIdx.x * 256 + threadIdx.x;        // 0 .. 128*2048
    int b = idx / ENCD, e = idx % ENCD;
    const float* base = d_encs + (size_t)b * PPS * ENCD + e;
    float s = 0.f;
    #pragma unroll 4
    for (int p = 0; p < PPS; ++p) s += base[(size_t)p * ENCD];
    d_mean[idx] = s * (1.0f / (float)PPS);
}

// ---------------------------------------------------------------------------
// Weight concatenation copies (float4) + bias sums
// ---------------------------------------------------------------------------
__global__ void w1copy_kernel(const float* __restrict__ l1Wih,
                              const float* __restrict__ l1Whh) {
    int g = blockIdx.x * 256 + threadIdx.x;          // float4 over 4096x2048
    int j = g / (2048 / 4);
    int c = (g % (2048 / 4)) * 4;
    float4 v;
    if (c < 1024) v = *(const float4*)(l1Wih + (size_t)j * 4096 + 1024 + c);
    else          v = *(const float4*)(l1Whh + (size_t)j * 1024 + (c - 1024));
    *(float4*)(d_W1cat + (size_t)j * 2048 + c) = v;
}

__global__ void w2copy_kernel(const float* __restrict__ l2Wih,
                              const float* __restrict__ l2Whh) {
    int g = blockIdx.x * 256 + threadIdx.x;          // float4 over 4096x4096
    int j = g / (4096 / 4);
    int c = (g % (4096 / 4)) * 4;
    float4 v;
    if (c < 3072) v = *(const float4*)(l2Wih + (size_t)j * 3072 + c);
    else          v = *(const float4*)(l2Whh + (size_t)j * 1024 + (c - 3072));
    *(float4*)(d_W2cat + (size_t)j * 4096 + c) = v;
}

__global__ void w3copy_kernel(const float* __restrict__ daW,
                              const float* __restrict__ fbW) {
    int g = blockIdx.x * 256 + threadIdx.x;          // float4 over 3072x1024
    int j = g / (1024 / 4);
    int c = (g % (1024 / 4)) * 4;
    float4 v;
    if (j < 1024) v = *(const float4*)(daW + (size_t)j * 1024 + c);
    else          v = *(const float4*)(fbW + (size_t)(j - 1024) * 1024 + c);
    *(float4*)(d_W3cat + (size_t)j * 1024 + c) = v;
}

__global__ void bias_kernel(const float* __restrict__ l1bih,
                            const float* __restrict__ l1bhh,
                            const float* __restrict__ l2bih,
                            const float* __restrict__ l2bhh,
                            const float* __restrict__ dab,
                            const float* __restrict__ fbb) {
    int j = blockIdx.x * 256 + threadIdx.x;          // 0..4095
    d_b1sum[j] = l1bih[j] + l1bhh[j];
    d_b2sum[j] = l2bih[j] + l2bhh[j];
    if (j < 3072) d_b3cat[j] = (j < 1024) ? dab[j] : fbb[j - 1024];
}

// ---------------------------------------------------------------------------
// Gather token embeddings: one block per row (t*128+b)
// ---------------------------------------------------------------------------
__global__ void embg_kernel(const float* __restrict__ emb) {
    int m = blockIdx.x;
    int tok = d_tokens[m];
    const float4* src = (const float4*)(emb + (size_t)tok * DHID);
    float4* dst = (float4*)(d_embg + (size_t)m * DHID);
    dst[threadIdx.x] = src[threadIdx.x];
}

// ---------------------------------------------------------------------------
// Zero initial states
// ---------------------------------------------------------------------------
__global__ void zero_kernel() {
    int idx = blockIdx.x * 256 + threadIdx.x;        // 0 .. 524287
    d_x2[idx] = 0.f;
    if (idx < BBS * 2048) d_x1[idx] = 0.f;
    if (idx < BBS * DHID) { d_c1[idx] = 0.f; d_c2[idx] = 0.f; }
}

// ---------------------------------------------------------------------------
// TF32x3 tensor-core GEMM: C[m,n] = sum_k A[m,k]*B[n,k] (+bias) (+adds)
// A split into hi/lo tf32 parts; 3 MMAs give ~fp32 accuracy at tensor speed.
// BM x BN block tile, BK=16, warp tile WM x WN (m16n16k8 wmma fragments).
// PRED variant: permuted masked store into the predictions output.
// All M,N,K at call sites are multiples of BM/BN/BK respectively.
// ---------------------------------------------------------------------------
template<int BM, int BN, int WM, int WN, bool BIAS, int NADD, bool PRED>
__global__ void gemm_tf32(const float* __restrict__ A,
                          const float* __restrict__ Bm,
                          const float* __restrict__ bias,
                          const float* __restrict__ add0,
                          const float* __restrict__ add1,
                          float* __restrict__ C,
                          int N, int K, int lda, int ldb, int ldc) {
    constexpr int BK = 16;
    constexpr int LDT = BK + 8;                      // 24: pad, 16B-multiple
    constexpr int WARPS_M = BM / WM;
    constexpr int WARPS_N = BN / WN;
    constexpr int NTH = WARPS_M * WARPS_N * 32;
    constexpr int MFR = WM / 16;
    constexpr int NFR = WN / 16;
    constexpr int SM_A = BM * LDT;
    constexpr int SM_B = BN * LDT;
    constexpr int SMEMF = (2 * SM_A + 2 * SM_B) > (BM * BN)
                        ? (2 * SM_A + 2 * SM_B) : (BM * BN);
    __shared__ float smem[SMEMF];
    float* Ah = smem;
    float* Al = smem + SM_A;
    float* Bh = smem + 2 * SM_A;
    float* Bl = smem + 2 * SM_A + SM_B;

    const int tid  = threadIdx.x;
    const int warp = tid >> 5;
    const int wm = (warp / WARPS_N) * WM;
    const int wn = (warp % WARPS_N) * WN;
    const int m0 = blockIdx.y * BM;
    const int n0 = blockIdx.x * BN;

    wmma::fragment<wmma::accumulator, 16, 16, 8, float> cf[MFR][NFR];
    #pragma unroll
    for (int i = 0; i < MFR; ++i)
        #pragma unroll
        for (int j = 0; j < NFR; ++j)
            wmma::fill_fragment(cf[i][j], 0.0f);

    for (int k0 = 0; k0 < K; k0 += BK) {
        // cooperative hi/lo split load of A tile
        #pragma unroll
        for (int i = tid; i < BM * BK / 4; i += NTH) {
            int m  = i / (BK / 4);
            int kq = (i % (BK / 4)) * 4;
            float4 v = *(const float4*)(A + (size_t)(m0 + m) * lda + k0 + kq);
            float h0 = tf32r(v.x), h1 = tf32r(v.y), h2 = tf32r(v.z), h3 = tf32r(v.w);
            float* ph = Ah + m * LDT + kq;
            float* pl = Al + m * LDT + kq;
            ph[0] = h0; ph[1] = h1; ph[2] = h2; ph[3] = h3;
            pl[0] = tf32r(v.x - h0); pl[1] = tf32r(v.y - h1);
            pl[2] = tf32r(v.z - h2); pl[3] = tf32r(v.w - h3);
        }
        // cooperative hi/lo split load of B tile
        #pragma unroll
        for (int i = tid; i < BN * BK / 4; i += NTH) {
            int n  = i / (BK / 4);
            int kq = (i % (BK / 4)) * 4;
            float4 v = *(const float4*)(Bm + (size_t)(n0 + n) * ldb + k0 + kq);
            float h0 = tf32r(v.x), h1 = tf32r(v.y), h2 = tf32r(v.z), h3 = tf32r(v.w);
            float* ph = Bh + n * LDT + kq;
            float* pl = Bl + n * LDT + kq;
            ph[0] = h0; ph[1] = h1; ph[2] = h2; ph[3] = h3;
            pl[0] = tf32r(v.x - h0); pl[1] = tf32r(v.y - h1);
            pl[2] = tf32r(v.z - h2); pl[3] = tf32r(v.w - h3);
        }
        __syncthreads();

        #pragma unroll
        for (int kk = 0; kk < BK; kk += 8) {
            wmma::fragment<wmma::matrix_a, 16, 16, 8, wmma::precision::tf32,
                           wmma::row_major> ah[MFR], al[MFR];
            wmma::fragment<wmma::matrix_b, 16, 16, 8, wmma::precision::tf32,
                           wmma::col_major> bh[NFR], bl[NFR];
            #pragma unroll
            for (int i = 0; i < MFR; ++i) {
                wmma::load_matrix_sync(ah[i], Ah + (wm + i * 16) * LDT + kk, LDT);
                wmma::load_matrix_sync(al[i], Al + (wm + i * 16) * LDT + kk, LDT);
            }
            #pragma unroll
            for (int j = 0; j < NFR; ++j) {
                wmma::load_matrix_sync(bh[j], Bh + (wn + j * 16) * LDT + kk, LDT);
                wmma::load_matrix_sync(bl[j], Bl + (wn + j * 16) * LDT + kk, LDT);
            }
            #pragma unroll
            for (int i = 0; i < MFR; ++i)
                #pragma unroll
                for (int j = 0; j < NFR; ++j) {
                    wmma::mma_sync(cf[i][j], ah[i], bh[j], cf[i][j]);
                    wmma::mma_sync(cf[i][j], al[i], bh[j], cf[i][j]);
                    wmma::mma_sync(cf[i][j], ah[i], bl[j], cf[i][j]);
                }
        }
        __syncthreads();
    }

    // stage results through shared (aliases tile buffers; all MMAs done)
    float* outs = smem;
    #pragma unroll
    for (int i = 0; i < MFR; ++i)
        #pragma unroll
        for (int j = 0; j < NFR; ++j)
            wmma::store_matrix_sync(outs + (wm + i * 16) * BN + (wn + j * 16),
                                    cf[i][j], BN, wmma::mem_row_major);
    __syncthreads();

    for (int i = tid; i < BM * BN; i += NTH) {
        int m = i / BN, n = i % BN;
        float v = outs[i];
        int gm = m0 + m, gn = n0 + n;
        if (BIAS)      v += bias[gn];
        if (NADD >= 1) v += add0[(size_t)gm * ldc + gn];
        if (NADD >= 2) v += add1[(size_t)gm * ldc + gn];
        if (PRED) {
            int t = gm / BBS, b = gm % BBS;
            C[(long long)(b * TTS + t) * N + gn] = (t < d_declen[b]) ? v : 0.f;
        } else {
            C[(size_t)gm * ldc + gn] = v;
        }
    }
}

// ---------------------------------------------------------------------------
// LSTM pointwise kernels (gate order: i, f, g, o)
// ---------------------------------------------------------------------------
__global__ void lstm1_kernel(int t) {
    int idx = blockIdx.x * 256 + threadIdx.x;        // 0 .. 128*1024
    int b = idx / DHID, k = idx % DHID;
    const float* g = d_gates + (size_t)b * 4096;
    float ig = g[k], fg = g[1024 + k], gg = g[2048 + k], og = g[3072 + k];
    float c = d_c1[idx];
    float cn = sigf(fg) * c + sigf(ig) * tanhf(gg);
    float hn = sigf(og) * tanhf(cn);
    d_x2[(size_t)b * 4096 + 2048 + k] = hn;          // candidate h1n (unmasked)
    if (t < d_declen[b]) {
        d_c1[idx] = cn;
        d_x1[(size_t)b * 2048 + 1024 + k] = hn;      // carried h1 state
    }
}

__global__ void lstm2_kernel(int t) {
    int idx = blockIdx.x * 256 + threadIdx.x;
    int b = idx / DHID, k = idx % DHID;
    const float* g = d_gates + (size_t)b * 4096;
    float ig = g[k], fg = g[1024 + k], gg = g[2048 + k], og = g[3072 + k];
    float c = d_c2[idx];
    float cn = sigf(fg) * c + sigf(ig) * tanhf(gg);
    float hn = sigf(og) * tanhf(cn);
    d_h2all[(size_t)(t * BBS + b) * DHID + k] = hn;  // candidate (unmasked)
    if (t < d_declen[b]) {
        d_c2[idx] = cn;
        d_x1[(size_t)b * 2048 + k] = hn;             // carried h2 state
        d_x2[(size_t)b * 4096 + 3072 + k] = hn;
    }
}

// ---------------------------------------------------------------------------
// Fused attention: scores = tanh(att1 + att2) . w + b0; softmax over p;
// awe = alpha @ enc; x2.att = sigmoid(gate_logits) * awe.   One block per b.
// ---------------------------------------------------------------------------
__global__ void attn_kernel(const float* __restrict__ fullW,
                            const float* __restrict__ fullb) {
    __shared__ float s_a2[DHID];
    __shared__ float s_w [DHID];
    __shared__ float s_sc[PPS];
    __shared__ float s_red[256];
    const int b = blockIdx.x;
    const int tid = threadIdx.x;
    const int lane = tid & 31, warp = tid >> 5;

    for (int i = tid; i < DHID; i += 256) {
        s_a2[i] = d_ag[(size_t)b * 3072 + i];
        s_w[i]  = fullW[i];
    }
    __syncthreads();

    const float b0 = fullb[0];
    for (int p = warp; p < PPS; p += 8) {
        const float* row = d_att1 + ((size_t)b * PPS + p) * DHID;
        float s = 0.f;
        #pragma unroll 8
        for (int a = lane; a < DHID; a += 32)
            s += tanh_fast(row[a] + s_a2[a]) * s_w[a];
        #pragma unroll
        for (int o = 16; o > 0; o >>= 1)
            s += __shfl_down_sync(0xffffffffu, s, o);
        if (lane == 0) s_sc[p] = s + b0;
    }
    __syncthreads();

    // softmax over 196
    s_red[tid] = (tid < PPS) ? s_sc[tid] : -INFINITY;
    __syncthreads();
    for (int s = 128; s > 0; s >>= 1) {
        if (tid < s) s_red[tid] = fmaxf(s_red[tid], s_red[tid + s]);
        __syncthreads();
    }
    float mx = s_red[0];
    __syncthreads();
    float e = 0.f;
    if (tid < PPS) { e = __expf(s_sc[tid] - mx); }
    s_red[tid] = e;
    __syncthreads();
    for (int s = 128; s > 0; s >>= 1) {
        if (tid < s) s_red[tid] += s_red[tid + s];
        __syncthreads();
    }
    float inv = 1.0f / s_red[0];
    __syncthreads();
    if (tid < PPS) s_sc[tid] = e * inv;              // alpha
    __syncthreads();

    // awe + gate
    const float* encb = d_encs + (size_t)b * PPS * ENCD;
    for (int ei = tid; ei < ENCD; ei += 256) {
        float acc = 0.f;
        const float* col = encb + ei;
        #pragma unroll 4
        for (int p = 0; p < PPS; ++p)
            acc = fmaf(s_sc[p], col[(size_t)p * ENCD], acc);
        float gate = sigf(d_ag[(size_t)b * 3072 + 1024 + ei]);
        d_x2[(size_t)b * 4096 + ei] = gate * acc;
    }
}

// ---------------------------------------------------------------------------
// predicted_pos: one warp per (t,b) row
// ---------------------------------------------------------------------------
__global__ void rpm_kernel(const float* __restrict__ rpmW,
                           float* __restrict__ out) {
    int m = blockIdx.x * 8 + (threadIdx.x >> 5);
    if (m >= TTS * BBS) return;
    int lane = threadIdx.x & 31;
    int t = m / BBS, b = m % BBS;
    const float* h = d_h2all + (size_t)m * DHID;
    float s = 0.f;
    #pragma unroll 8
    for (int k = lane; k < DHID; k += 32) s += h[k] * rpmW[k];
    #pragma unroll
    for (int o = 16; o > 0; o >>= 1)
        s += __shfl_down_sync(0xffffffffu, s, o);
    if (lane == 0)
        out[O_PPOS + (long long)b * TTS + t] =
            (t < d_declen[b]) ? sigf(s) : 0.f;
}

// ---------------------------------------------------------------------------
// Launch
// ---------------------------------------------------------------------------
extern "C" void kernel_launch(void* const* d_in, const int* in_sizes, int n_in,
                              void* d_out, int out_size) {
    const float* enc_out = (const float*)d_in[0];
    const int*   caps    = (const int*)  d_in[1];
    const int*   caplen  = (const int*)  d_in[2];
    const float* emb     = (const float*)d_in[3];
    const float* eaW     = (const float*)d_in[4];
    const float* eab     = (const float*)d_in[5];
    const float* daW     = (const float*)d_in[6];
    const float* dab     = (const float*)d_in[7];
    const float* faW     = (const float*)d_in[8];
    const float* fab     = (const float*)d_in[9];
    const float* fbW     = (const float*)d_in[10];
    const float* fbb     = (const float*)d_in[11];
    const float* l1Wih   = (const float*)d_in[12];
    const float* l1Whh   = (const float*)d_in[13];
    const float* l1bih   = (const float*)d_in[14];
    const float* l1bhh   = (const float*)d_in[15];
    const float* l2Wih   = (const float*)d_in[16];
    const float* l2Whh   = (const float*)d_in[17];
    const float* l2bih   = (const float*)d_in[18];
    const float* l2bhh   = (const float*)d_in[19];
    const float* ramW    = (const float*)d_in[20];
    const float* ramb    = (const float*)d_in[21];
    const float* rpmW    = (const float*)d_in[22];
    float* out = (float*)d_out;

    float* p_encs;  cudaGetSymbolAddress((void**)&p_encs,  d_encs);
    float* p_att1;  cudaGetSymbolAddress((void**)&p_att1,  d_att1);
    float* p_econ;  cudaGetSymbolAddress((void**)&p_econ,  d_econ);
    float* p_embg;  cudaGetSymbolAddress((void**)&p_embg,  d_embg);
    float* p_W1;    cudaGetSymbolAddress((void**)&p_W1,    d_W1cat);
    float* p_W2;    cudaGetSymbolAddress((void**)&p_W2,    d_W2cat);
    float* p_W3;    cudaGetSymbolAddress((void**)&p_W3,    d_W3cat);
    float* p_b1;    cudaGetSymbolAddress((void**)&p_b1,    d_b1sum);
    float* p_b2;    cudaGetSymbolAddress((void**)&p_b2,    d_b2sum);
    float* p_b3;    cudaGetSymbolAddress((void**)&p_b3,    d_b3cat);
    float* p_base1; cudaGetSymbolAddress((void**)&p_base1, d_base1);
    float* p_gates; cudaGetSymbolAddress((void**)&p_gates, d_gates);
    float* p_x1;    cudaGetSymbolAddress((void**)&p_x1,    d_x1);
    float* p_x2;    cudaGetSymbolAddress((void**)&p_x2,    d_x2);
    float* p_ag;    cudaGetSymbolAddress((void**)&p_ag,    d_ag);
    float* p_mean;  cudaGetSymbolAddress((void**)&p_mean,  d_mean);
    float* p_h2;    cudaGetSymbolAddress((void**)&p_h2,    d_h2all);

    // 1. sort / small outputs / tokens
    setup_kernel<<<1, BBS>>>(caplen, caps, out);

    // 2. gather sorted encoder
    gather_enc_kernel<<<50176, 256>>>(enc_out);

    // 3. mean over pixels
    mean_kernel<<<(BBS * ENCD) / 256, 256>>>();

    // 4. weight concatenations + bias sums
    bias_kernel<<<4096 / 256, 256>>>(l1bih, l1bhh, l2bih, l2bhh, dab, fbb);
    w1copy_kernel<<<(4096 * 2048 / 4) / 256, 256>>>(l1Wih, l1Whh);
    w2copy_kernel<<<(4096 * 4096 / 4) / 256, 256>>>(l2Wih, l2Whh);
    w3copy_kernel<<<(3072 * 1024 / 4) / 256, 256>>>(daW, fbW);

    // 5. token embedding gather
    embg_kernel<<<TTS * BBS, 256>>>(emb);

    // 6. base1 = mean_enc @ Wih[:,2048:].T + (bih+bhh)   (128 x 4096, K=2048)
    gemm_tf32<64, 64, 32, 32, true, 0, false><<<dim3(4096 / 64, 2), 128>>>(
        p_mean, l1Wih + 2048, p_b1, nullptr, nullptr, p_base1,
        4096, 2048, 2048, 4096, 4096);

    // 7. econ = embg @ Wih[:,0:1024].T   (2688 x 4096, K=1024)
    gemm_tf32<128, 64, 32, 32, false, 0, false><<<dim3(4096 / 64, 21), 256>>>(
        p_embg, l1Wih, nullptr, nullptr, nullptr, p_econ,
        4096, 1024, 1024, 4096, 4096);

    // 8. att1 = enc_sorted @ enc_att_W.T + b   (25088 x 1024, K=2048)
    gemm_tf32<128, 64, 32, 32, true, 0, false><<<dim3(1024 / 64, 196), 256>>>(
        p_encs, eaW, eab, nullptr, nullptr, p_att1,
        1024, 2048, 2048, 2048, 1024);

    // 9. zero states
    zero_kernel<<<(BBS * 4096) / 256, 256>>>();

    // 10. sequential decode
    for (int t = 0; t < TTS; ++t) {
        // gates1 = [h2|h1] @ W1cat.T + base1 + econ[t]
        gemm_tf32<64, 64, 32, 32, false, 2, false><<<dim3(4096 / 64, 2), 128>>>(
            p_x1, p_W1, nullptr, p_base1, p_econ + (size_t)t * BBS * 4096,
            p_gates, 4096, 2048, 2048, 2048, 4096);

        lstm1_kernel<<<(BBS * DHID) / 256, 256>>>(t);

        // [att2 | gate logits] = h1n @ [dec_att_W ; f_beta_W].T + b3
        gemm_tf32<64, 64, 32, 32, true, 0, false><<<dim3(3072 / 64, 2), 128>>>(
            p_x2 + 2048, p_W3, p_b3, nullptr, nullptr, p_ag,
            3072, 1024, 4096, 1024, 3072);

        attn_kernel<<<BBS, 256>>>(faW, fab);

        // gates2 = [att|h1n|h2] @ [l2_Wih|l2_Whh].T + (bih+bhh)
        gemm_tf32<64, 64, 32, 32, true, 0, false><<<dim3(4096 / 64, 2), 128>>>(
            p_x2, p_W2, p_b2, nullptr, nullptr, p_gates,
            4096, 4096, 4096, 4096, 4096);

        lstm2_kernel<<<(BBS * DHID) / 256, 256>>>(t);
    }

    // 11. predictions = h2all @ ram_W.T + ram_b, permuted + masked store
    gemm_tf32<128, 64, 32, 32, true, 0, true><<<dim3(VOC / 64, 21), 256>>>(
        p_h2, ramW, ramb, nullptr, nullptr, out + O_PRED,
        VOC, 1024, 1024, 1024, VOC);

    // 12. predicted_pos
    rpm_kernel<<<(TTS * BBS + 7) / 8, 256>>>(rpmW, out);
}

// round 7
// speedup vs baseline: 1.4134x; 1.3975x over previous
#include <cuda_runtime.h>
#include <math.h>

// ---------------------------------------------------------------------------
// Problem constants
// ---------------------------------------------------------------------------
#define TTS   21      // Tm = CAP-1 decode steps
#define CAPL  22
#define BBS   128     // batch
#define PPS   196     // pixels
#define ENCD  2048
#define DHID  1024
#define VOC   32000

static constexpr long long O_PRED = 0;
static constexpr long long O_CAPS = (long long)BBS * TTS * VOC;   // 86,016,000
static constexpr long long O_DECL = O_CAPS + (long long)BBS * CAPL;
static constexpr long long O_SORT = O_DECL + BBS;
static constexpr long long O_RPOS = O_SORT + BBS;
static constexpr long long O_PPOS = O_RPOS + (long long)BBS * TTS;

// ---------------------------------------------------------------------------
// Static device scratch (no runtime allocation allowed)
// ---------------------------------------------------------------------------
__device__ float d_encs [(size_t)BBS * PPS * ENCD];   // sorted encoder
__device__ float d_att1 [(size_t)BBS * PPS * DHID];   // att1
__device__ float d_econ [(size_t)TTS * BBS * 4 * DHID]; // embed @ Wih_e^T
__device__ float d_embg [(size_t)TTS * BBS * DHID];   // gathered embeddings
__device__ float d_W1cat[4096 * 2048];                // [Wih(:,1024:2048) | Whh]
__device__ float d_W2cat[(size_t)4096 * 4096];        // [l2_Wih | l2_Whh]
__device__ float d_W3cat[3072 * 1024];                // [dec_att_W ; f_beta_W]
__device__ float d_b1sum[4096];
__device__ float d_b2sum[4096];
__device__ float d_b3cat[3072];
__device__ float d_base1[BBS * 4096];                 // biases + mean_enc contrib
__device__ float d_gates[BBS * 4096];
__device__ float d_x1   [BBS * 2048];                 // [h2_state | h1_state]
__device__ float d_x2   [BBS * 4096];                 // [att | h1n | h2_state]
__device__ float d_ag   [BBS * 3072];                 // [att2 | gate logits]
__device__ float d_c1   [BBS * DHID];
__device__ float d_c2   [BBS * DHID];
__device__ float d_mean [BBS * ENCD];
__device__ float d_h2all[(size_t)TTS * BBS * DHID];   // h2n (active rows only)
__device__ int   d_sort  [BBS];
__device__ int   d_declen[BBS];
__device__ int   d_tokens[TTS * BBS];
__device__ int   d_nact  [TTS];                       // active prefix size per t
__device__ int   d_rowidx[TTS * BBS];                 // compact -> t*BBS+b
__device__ int   d_outrow[TTS * BBS];                 // compact -> b*TTS+t
__device__ int   d_cnt;                               // number of active pairs

// ---------------------------------------------------------------------------
// Math helpers
// ---------------------------------------------------------------------------
__device__ __forceinline__ float sigf(float x) {
    return 1.0f / (1.0f + __expf(-x));
}
__device__ __forceinline__ float tanh_fast(float x) {
    return 1.0f - 2.0f / (__expf(2.0f * x) + 1.0f);
}

// ---------------------------------------------------------------------------
// Setup: stable descending argsort; caps/dec_len/sort/rel_pos out; active
// prefix sizes and compact active-row lists.
// ---------------------------------------------------------------------------
__global__ void setup_kernel(const int* __restrict__ caplen,
                             const int* __restrict__ caps,
                             float* __restrict__ out) {
    __shared__ int lens_s[BBS];
    __shared__ int sort_s[BBS];
    __shared__ int dl_s[BBS];
    int i = threadIdx.x;
    int li = caplen[i];
    lens_s[i] = li;
    __syncthreads();
    int rank = 0;
    for (int j = 0; j < BBS; ++j) {
        int lj = lens_s[j];
        if (lj > li || (lj == li && j < i)) rank++;
    }
    sort_s[rank] = i;
    __syncthreads();
    int src = sort_s[i];
    d_sort[i] = src;
    int dl = lens_s[src] - 1;
    d_declen[i] = dl;
    dl_s[i] = dl;
    out[O_DECL + i] = (float)dl;
    out[O_SORT + i] = (float)src;
    for (int t = 0; t < CAPL; ++t) {
        int tok = caps[src * CAPL + t];
        out[O_CAPS + (long long)i * CAPL + t] = (float)tok;
        if (t < TTS) d_tokens[t * BBS + i] = tok;
    }
    float dlf = (float)dl;
    for (int s = 0; s < TTS; ++s)
        out[O_RPOS + (long long)i * TTS + s] =
            (s < dl) ? ((float)(s + 1) / dlf) : 0.0f;
    __syncthreads();
    if (i == 0) {
        int c = 0;
        for (int t = 0; t < TTS; ++t) {
            int n = 0;
            while (n < BBS && dl_s[n] > t) n++;   // dl_s sorted descending
            d_nact[t] = n;
            for (int b = 0; b < n; ++b) {
                d_rowidx[c] = t * BBS + b;
                d_outrow[c] = b * TTS + t;
                c++;
            }
        }
        d_cnt = c;
    }
}

// ---------------------------------------------------------------------------
// Gather sorted encoder rows (float4)
// ---------------------------------------------------------------------------
__global__ void gather_enc_kernel(const float* __restrict__ enc) {
    int g = blockIdx.x * 256 + threadIdx.x;
    const int V4ROW = ENCD / 4;                      // 512
    int r = g / V4ROW;
    int w = g % V4ROW;
    int b = r / PPS, p = r % PPS;
    int srow = d_sort[b] * PPS + p;
    const float4* src = (const float4*)enc;
    float4* dst = (float4*)d_encs;
    dst[(size_t)r * V4ROW + w] = src[(size_t)srow * V4ROW + w];
}

// ---------------------------------------------------------------------------
// mean over pixels: one thread per (b,e)
// ---------------------------------------------------------------------------
__global__ void mean_kernel() {
    int idx = blockIdx.x * 256 + threadIdx.x;
    int b = idx / ENCD, e = idx % ENCD;
    const float* base = d_encs + (size_t)b * PPS * ENCD + e;
    float s = 0.f;
    #pragma unroll 4
    for (int p = 0; p < PPS; ++p) s += base[(size_t)p * ENCD];
    d_mean[idx] = s * (1.0f / (float)PPS);
}

// ---------------------------------------------------------------------------
// Weight concatenation copies (float4) + bias sums
// ---------------------------------------------------------------------------
__global__ void w1copy_kernel(const float* __restrict__ l1Wih,
                              const float* __restrict__ l1Whh) {
    int g = blockIdx.x * 256 + threadIdx.x;
    int j = g / (2048 / 4);
    int c = (g % (2048 / 4)) * 4;
    float4 v;
    if (c < 1024) v = *(const float4*)(l1Wih + (size_t)j * 4096 + 1024 + c);
    else          v = *(const float4*)(l1Whh + (size_t)j * 1024 + (c - 1024));
    *(float4*)(d_W1cat + (size_t)j * 2048 + c) = v;
}

__global__ void w2copy_kernel(const float* __restrict__ l2Wih,
                              const float* __restrict__ l2Whh) {
    int g = blockIdx.x * 256 + threadIdx.x;
    int j = g / (4096 / 4);
    int c = (g % (4096 / 4)) * 4;
    float4 v;
    if (c < 3072) v = *(const float4*)(l2Wih + (size_t)j * 3072 + c);
    else          v = *(const float4*)(l2Whh + (size_t)j * 1024 + (c - 3072));
    *(float4*)(d_W2cat + (size_t)j * 4096 + c) = v;
}

__global__ void w3copy_kernel(const float* __restrict__ daW,
                              const float* __restrict__ fbW) {
    int g = blockIdx.x * 256 + threadIdx.x;
    int j = g / (1024 / 4);
    int c = (g % (1024 / 4)) * 4;
    float4 v;
    if (j < 1024) v = *(const float4*)(daW + (size_t)j * 1024 + c);
    else          v = *(const float4*)(fbW + (size_t)(j - 1024) * 1024 + c);
    *(float4*)(d_W3cat + (size_t)j * 1024 + c) = v;
}

__global__ void bias_kernel(const float* __restrict__ l1bih,
                            const float* __restrict__ l1bhh,
                            const float* __restrict__ l2bih,
                            const float* __restrict__ l2bhh,
                            const float* __restrict__ dab,
                            const float* __restrict__ fbb) {
    int j = blockIdx.x * 256 + threadIdx.x;
    d_b1sum[j] = l1bih[j] + l1bhh[j];
    d_b2sum[j] = l2bih[j] + l2bhh[j];
    if (j < 3072) d_b3cat[j] = (j < 1024) ? dab[j] : fbb[j - 1024];
}

// ---------------------------------------------------------------------------
// Gather token embeddings: one block per (t,b) row
// ---------------------------------------------------------------------------
__global__ void embg_kernel(const float* __restrict__ emb) {
    int m = blockIdx.x;
    int tok = d_tokens[m];
    const float4* src = (const float4*)(emb + (size_t)tok * DHID);
    float4* dst = (float4*)(d_embg + (size_t)m * DHID);
    dst[threadIdx.x] = src[threadIdx.x];
}

// ---------------------------------------------------------------------------
// Zero initial states / zero the whole predictions region
// ---------------------------------------------------------------------------
__global__ void zero_states_kernel() {
    int idx = blockIdx.x * 256 + threadIdx.x;        // 0 .. 524287
    d_x2[idx] = 0.f;
    if (idx < BBS * 2048) d_x1[idx] = 0.f;
    if (idx < BBS * DHID) { d_c1[idx] = 0.f; d_c2[idx] = 0.f; }
}

__global__ void zero_pred_kernel(float* __restrict__ out) {
    size_t g = (size_t)blockIdx.x * 256 + threadIdx.x;  // float4 index
    ((float4*)out)[g] = make_float4(0.f, 0.f, 0.f, 0.f);
}

// ---------------------------------------------------------------------------
// Big GEMM: 128x128 tile, BK=16, 256 threads, 8x8 microtile. fp32.
// C[m,n] = sum_k A[m,k]*B[n,k]  (A row-major lda, B row-major ldb over k)
// MODE 0: plain   MODE 1: +bias[n]
// MODE 2: +bias, A-rows gathered via d_rowidx, stores scattered via d_outrow,
//         rows >= d_cnt skipped (predictions path).
// ---------------------------------------------------------------------------
template<int MODE>
__global__ void __launch_bounds__(256)
gemm128(const float* __restrict__ A,
        const float* __restrict__ Bm,
        const float* __restrict__ bias,
        float* __restrict__ C,
        int N, int K, int lda, int ldb, int ldc) {
    __shared__ float As[16][132];
    __shared__ float Bs[16][132];
    const int tid = threadIdx.x;
    const int m0 = blockIdx.y * 128;
    const int n0 = blockIdx.x * 128;
    int count = 0;
    if (MODE == 2) {
        count = d_cnt;
        if (m0 >= count) return;
    }
    const int lr = tid >> 1;            // load row 0..127
    const int lc = (tid & 1) * 8;       // col base 0 or 8
    int arow = m0 + lr;
    if (MODE == 2) arow = (m0 + lr < count) ? d_rowidx[m0 + lr] : d_rowidx[0];
    const float* Aptr = A + (size_t)arow * lda + lc;
    const float* Bptr = Bm + (size_t)(n0 + lr) * ldb + lc;

    const int ty = tid >> 4;            // 0..15 (m)
    const int tx = tid & 15;            // 0..15 (n)

    float acc[8][8];
    #pragma unroll
    for (int i = 0; i < 8; ++i)
        #pragma unroll
        for (int j = 0; j < 8; ++j) acc[i][j] = 0.f;

    for (int k0 = 0; k0 < K; k0 += 16) {
        float4 a0 = *(const float4*)(Aptr + k0);
        float4 a1 = *(const float4*)(Aptr + k0 + 4);
        float4 b0 = *(const float4*)(Bptr + k0);
        float4 b1 = *(const float4*)(Bptr + k0 + 4);
        As[lc + 0][lr] = a0.x; As[lc + 1][lr] = a0.y;
        As[lc + 2][lr] = a0.z; As[lc + 3][lr] = a0.w;
        As[lc + 4][lr] = a1.x; As[lc + 5][lr] = a1.y;
        As[lc + 6][lr] = a1.z; As[lc + 7][lr] = a1.w;
        Bs[lc + 0][lr] = b0.x; Bs[lc + 1][lr] = b0.y;
        Bs[lc + 2][lr] = b0.z; Bs[lc + 3][lr] = b0.w;
        Bs[lc + 4][lr] = b1.x; Bs[lc + 5][lr] = b1.y;
        Bs[lc + 6][lr] = b1.z; Bs[lc + 7][lr] = b1.w;
        __syncthreads();
        #pragma unroll
        for (int kk = 0; kk < 16; ++kk) {
            float a[8], b[8];
            *(float4*)(a)     = *(const float4*)&As[kk][ty * 8];
            *(float4*)(a + 4) = *(const float4*)&As[kk][ty * 8 + 4];
            *(float4*)(b)     = *(const float4*)&Bs[kk][tx * 8];
            *(float4*)(b + 4) = *(const float4*)&Bs[kk][tx * 8 + 4];
            #pragma unroll
            for (int i = 0; i < 8; ++i)
                #pragma unroll
                for (int j = 0; j < 8; ++j)
                    acc[i][j] = fmaf(a[i], b[j], acc[i][j]);
        }
        __syncthreads();
    }

    float bv[8];
    #pragma unroll
    for (int j = 0; j < 8; ++j)
        bv[j] = (MODE >= 1) ? bias[n0 + tx * 8 + j] : 0.f;

    #pragma unroll
    for (int i = 0; i < 8; ++i) {
        int m = m0 + ty * 8 + i;
        long long crow = m;
        if (MODE == 2) {
            if (m >= count) continue;
            crow = d_outrow[m];
        }
        float* dst = C + crow * (long long)ldc + n0 + tx * 8;
        float4 v0, v1;
        v0.x = acc[i][0] + bv[0]; v0.y = acc[i][1] + bv[1];
        v0.z = acc[i][2] + bv[2]; v0.w = acc[i][3] + bv[3];
        v1.x = acc[i][4] + bv[4]; v1.y = acc[i][5] + bv[5];
        v1.z = acc[i][6] + bv[6]; v1.w = acc[i][7] + bv[7];
        *(float4*)(dst)     = v0;
        *(float4*)(dst + 4) = v1;
    }
}

// ---------------------------------------------------------------------------
// Skinny GEMM: 32x128 tile, BK=16, 128 threads, 4x8 microtile. fp32.
// MODE 0: +bias[n]    MODE 1: +add0[m,n] + add1[m,n]  (stride ldc)
// t >= 0: early-exit blocks whose rows are entirely inactive (m0 >= nact[t]).
// ---------------------------------------------------------------------------
template<int MODE>
__global__ void __launch_bounds__(128)
gemm32(const float* __restrict__ A,
       const float* __restrict__ Bm,
       const float* __restrict__ bias,
       const float* __restrict__ add0,
       const float* __restrict__ add1,
       float* __restrict__ C,
       int N, int K, int lda, int ldb, int ldc, int t) {
    const int m0 = blockIdx.y * 32;
    if (t >= 0 && m0 >= d_nact[t]) return;
    __shared__ float As[16][36];
    __shared__ float Bs[16][132];
    const int tid = threadIdx.x;
    const int n0 = blockIdx.x * 128;

    const int ar = tid >> 2;            // A load row 0..31
    const int ac = (tid & 3) * 4;       // A col 0,4,8,12
    const float* Aptr = A + (size_t)(m0 + ar) * lda + ac;
    const float* Bptr = Bm + (size_t)(n0 + tid) * ldb;

    const int ty = tid >> 4;            // 0..7  (m)
    const int tx = tid & 15;            // 0..15 (n)

    float acc[4][8];
    #pragma unroll
    for (int i = 0; i < 4; ++i)
        #pragma unroll
        for (int j = 0; j < 8; ++j) acc[i][j] = 0.f;

    for (int k0 = 0; k0 < K; k0 += 16) {
        float4 av = *(const float4*)(Aptr + k0);
        As[ac + 0][ar] = av.x; As[ac + 1][ar] = av.y;
        As[ac + 2][ar] = av.z; As[ac + 3][ar] = av.w;
        #pragma unroll
        for (int j = 0; j < 4; ++j) {
            float4 bvv = *(const float4*)(Bptr + k0 + j * 4);
            Bs[j * 4 + 0][tid] = bvv.x; Bs[j * 4 + 1][tid] = bvv.y;
            Bs[j * 4 + 2][tid] = bvv.z; Bs[j * 4 + 3][tid] = bvv.w;
        }
        __syncthreads();
        #pragma unroll
        for (int kk = 0; kk < 16; ++kk) {
            float a[4], b[8];
            *(float4*)(a)     = *(const float4*)&As[kk][ty * 4];
            *(float4*)(b)     = *(const float4*)&Bs[kk][tx * 8];
            *(float4*)(b + 4) = *(const float4*)&Bs[kk][tx * 8 + 4];
            #pragma unroll
            for (int i = 0; i < 4; ++i)
                #pragma unroll
                for (int j = 0; j < 8; ++j)
                    acc[i][j] = fmaf(a[i], b[j], acc[i][j]);
        }
        __syncthreads();
    }

    float bv[8];
    #pragma unroll
    for (int j = 0; j < 8; ++j)
        bv[j] = (MODE == 0) ? bias[n0 + tx * 8 + j] : 0.f;

    #pragma unroll
    for (int i = 0; i < 4; ++i) {
        int m = m0 + ty * 4 + i;
        float* dst = C + (size_t)m * ldc + n0 + tx * 8;
        float add[8];
        if (MODE == 1) {
            const float* a0p = add0 + (size_t)m * ldc + n0 + tx * 8;
            const float* a1p = add1 + (size_t)m * ldc + n0 + tx * 8;
            #pragma unroll
            for (int j = 0; j < 8; ++j) add[j] = a0p[j] + a1p[j];
        } else {
            #pragma unroll
            for (int j = 0; j < 8; ++j) add[j] = bv[j];
        }
        float4 v0, v1;
        v0.x = acc[i][0] + add[0]; v0.y = acc[i][1] + add[1];
        v0.z = acc[i][2] + add[2]; v0.w = acc[i][3] + add[3];
        v1.x = acc[i][4] + add[4]; v1.y = acc[i][5] + add[5];
        v1.z = acc[i][6] + add[6]; v1.w = acc[i][7] + add[7];
        *(float4*)(dst)     = v0;
        *(float4*)(dst + 4) = v1;
    }
}

// ---------------------------------------------------------------------------
// LSTM pointwise kernels (gate order: i, f, g, o). Inactive rows skipped.
// ---------------------------------------------------------------------------
__global__ void lstm1_kernel(int t) {
    int idx = blockIdx.x * 256 + threadIdx.x;
    int b = idx / DHID, k = idx % DHID;
    if (t >= d_declen[b]) return;
    const float* g = d_gates + (size_t)b * 4096;
    float ig = g[k], fg = g[1024 + k], gg = g[2048 + k], og = g[3072 + k];
    float c = d_c1[idx];
    float cn = sigf(fg) * c + sigf(ig) * tanhf(gg);
    float hn = sigf(og) * tanhf(cn);
    d_c1[idx] = cn;
    d_x1[(size_t)b * 2048 + 1024 + k] = hn;          // carried h1 state
    d_x2[(size_t)b * 4096 + 2048 + k] = hn;          // h1n for att2/gates2
}

__global__ void lstm2_kernel(int t) {
    int idx = blockIdx.x * 256 + threadIdx.x;
    int b = idx / DHID, k = idx % DHID;
    if (t >= d_declen[b]) return;
    const float* g = d_gates + (size_t)b * 4096;
    float ig = g[k], fg = g[1024 + k], gg = g[2048 + k], og = g[3072 + k];
    float c = d_c2[idx];
    float cn = sigf(fg) * c + sigf(ig) * tanhf(gg);
    float hn = sigf(og) * tanhf(cn);
    d_c2[idx] = cn;
    d_h2all[(size_t)(t * BBS + b) * DHID + k] = hn;
    d_x1[(size_t)b * 2048 + k] = hn;                 // carried h2 state
    d_x2[(size_t)b * 4096 + 3072 + k] = hn;
}

// ---------------------------------------------------------------------------
// Fused attention: scores = tanh(att1 + att2) . w + b0; softmax over p;
// awe = alpha @ enc; x2.att = sigmoid(gate_logits) * awe.  One block per b.
// ---------------------------------------------------------------------------
__global__ void attn_kernel(const float* __restrict__ fullW,
                            const float* __restrict__ fullb, int t) {
    const int b = blockIdx.x;
    if (t >= d_declen[b]) return;
    __shared__ float s_a2[DHID];
    __shared__ float s_w [DHID];
    __shared__ float s_sc[PPS];
    __shared__ float s_red[256];
    const int tid = threadIdx.x;
    const int lane = tid & 31, warp = tid >> 5;

    for (int i = tid; i < DHID; i += 256) {
        s_a2[i] = d_ag[(size_t)b * 3072 + i];
        s_w[i]  = fullW[i];
    }
    __syncthreads();

    const float b0 = fullb[0];
    for (int p = warp; p < PPS; p += 8) {
        const float* row = d_att1 + ((size_t)b * PPS + p) * DHID;
        float s = 0.f;
        #pragma unroll 8
        for (int a = lane; a < DHID; a += 32)
            s += tanh_fast(row[a] + s_a2[a]) * s_w[a];
        #pragma unroll
        for (int o = 16; o > 0; o >>= 1)
            s += __shfl_down_sync(0xffffffffu, s, o);
        if (lane == 0) s_sc[p] = s + b0;
    }
    __syncthreads();

    s_red[tid] = (tid < PPS) ? s_sc[tid] : -INFINITY;
    __syncthreads();
    for (int s = 128; s > 0; s >>= 1) {
        if (tid < s) s_red[tid] = fmaxf(s_red[tid], s_red[tid + s]);
        __syncthreads();
    }
    float mx = s_red[0];
    __syncthreads();
    float e = 0.f;
    if (tid < PPS) e = __expf(s_sc[tid] - mx);
    s_red[tid] = e;
    __syncthreads();
    for (int s = 128; s > 0; s >>= 1) {
        if (tid < s) s_red[tid] += s_red[tid + s];
        __syncthreads();
    }
    float inv = 1.0f / s_red[0];
    __syncthreads();
    if (tid < PPS) s_sc[tid] = e * inv;
    __syncthreads();

    const float* encb = d_encs + (size_t)b * PPS * ENCD;
    for (int ei = tid; ei < ENCD; ei += 256) {
        float acc = 0.f;
        const float* col = encb + ei;
        #pragma unroll 4
        for (int p = 0; p < PPS; ++p)
            acc = fmaf(s_sc[p], col[(size_t)p * ENCD], acc);
        float gate = sigf(d_ag[(size_t)b * 3072 + 1024 + ei]);
        d_x2[(size_t)b * 4096 + ei] = gate * acc;
    }
}

// ---------------------------------------------------------------------------
// predicted_pos: one warp per (t,b) row
// ---------------------------------------------------------------------------
__global__ void rpm_kernel(const float* __restrict__ rpmW,
                           float* __restrict__ out) {
    int m = blockIdx.x * 8 + (threadIdx.x >> 5);
    if (m >= TTS * BBS) return;
    int lane = threadIdx.x & 31;
    int t = m / BBS, b = m % BBS;
    const float* h = d_h2all + (size_t)m * DHID;
    float s = 0.f;
    #pragma unroll 8
    for (int k = lane; k < DHID; k += 32) s += h[k] * rpmW[k];
    #pragma unroll
    for (int o = 16; o > 0; o >>= 1)
        s += __shfl_down_sync(0xffffffffu, s, o);
    if (lane == 0)
        out[O_PPOS + (long long)b * TTS + t] =
            (t < d_declen[b]) ? sigf(s) : 0.f;
}

// ---------------------------------------------------------------------------
// Launch
// ---------------------------------------------------------------------------
extern "C" void kernel_launch(void* const* d_in, const int* in_sizes, int n_in,
                              void* d_out, int out_size) {
    const float* enc_out = (const float*)d_in[0];
    const int*   caps    = (const int*)  d_in[1];
    const int*   caplen  = (const int*)  d_in[2];
    const float* emb     = (const float*)d_in[3];
    const float* eaW     = (const float*)d_in[4];
    const float* eab     = (const float*)d_in[5];
    const float* daW     = (const float*)d_in[6];
    const float* dab     = (const float*)d_in[7];
    const float* faW     = (const float*)d_in[8];
    const float* fab     = (const float*)d_in[9];
    const float* fbW     = (const float*)d_in[10];
    const float* fbb     = (const float*)d_in[11];
    const float* l1Wih   = (const float*)d_in[12];
    const float* l1Whh   = (const float*)d_in[13];
    const float* l1bih   = (const float*)d_in[14];
    const float* l1bhh   = (const float*)d_in[15];
    const float* l2Wih   = (const float*)d_in[16];
    const float* l2Whh   = (const float*)d_in[17];
    const float* l2bih   = (const float*)d_in[18];
    const float* l2bhh   = (const float*)d_in[19];
    const float* ramW    = (const float*)d_in[20];
    const float* ramb    = (const float*)d_in[21];
    const float* rpmW    = (const float*)d_in[22];
    float* out = (float*)d_out;

    float* p_encs;  cudaGetSymbolAddress((void**)&p_encs,  d_encs);
    float* p_att1;  cudaGetSymbolAddress((void**)&p_att1,  d_att1);
    float* p_econ;  cudaGetSymbolAddress((void**)&p_econ,  d_econ);
    float* p_embg;  cudaGetSymbolAddress((void**)&p_embg,  d_embg);
    float* p_W1;    cudaGetSymbolAddress((void**)&p_W1,    d_W1cat);
    float* p_W2;    cudaGetSymbolAddress((void**)&p_W2,    d_W2cat);
    float* p_W3;    cudaGetSymbolAddress((void**)&p_W3,    d_W3cat);
    float* p_b1;    cudaGetSymbolAddress((void**)&p_b1,    d_b1sum);
    float* p_b2;    cudaGetSymbolAddress((void**)&p_b2,    d_b2sum);
    float* p_b3;    cudaGetSymbolAddress((void**)&p_b3,    d_b3cat);
    float* p_base1; cudaGetSymbolAddress((void**)&p_base1, d_base1);
    float* p_gates; cudaGetSymbolAddress((void**)&p_gates, d_gates);
    float* p_x1;    cudaGetSymbolAddress((void**)&p_x1,    d_x1);
    float* p_x2;    cudaGetSymbolAddress((void**)&p_x2,    d_x2);
    float* p_ag;    cudaGetSymbolAddress((void**)&p_ag,    d_ag);
    float* p_mean;  cudaGetSymbolAddress((void**)&p_mean,  d_mean);
    float* p_h2;    cudaGetSymbolAddress((void**)&p_h2,    d_h2all);

    // 1-3: sort, gather encoder, mean
    setup_kernel<<<1, BBS>>>(caplen, caps, out);
    gather_enc_kernel<<<50176, 256>>>(enc_out);
    mean_kernel<<<(BBS * ENCD) / 256, 256>>>();

    // 4: att1 = enc_sorted @ enc_att_W.T + b  (25088 x 1024, K=2048)
    //    (placed here so ncu -s 5 -c 1 captures this representative GEMM)
    gemm128<1><<<dim3(1024 / 128, (BBS * PPS) / 128), 256>>>(
        p_encs, eaW, eab, p_att1, 1024, 2048, 2048, 2048, 1024);

    // 5: zero whole predictions region (inactive rows stay 0)
    zero_pred_kernel<<<84000, 256>>>(out + O_PRED);

    // 6-9: bias sums + weight concatenations
    bias_kernel<<<16, 256>>>(l1bih, l1bhh, l2bih, l2bhh, dab, fbb);
    w1copy_kernel<<<8192, 256>>>(l1Wih, l1Whh);
    w2copy_kernel<<<16384, 256>>>(l2Wih, l2Whh);
    w3copy_kernel<<<3072, 256>>>(daW, fbW);

    // 10: token embedding gather
    embg_kernel<<<TTS * BBS, 256>>>(emb);

    // 11: base1 = mean_enc @ Wih[:,2048:].T + (bih+bhh)  (128 x 4096, K=2048)
    gemm32<0><<<dim3(4096 / 128, 4), 128>>>(
        p_mean, l1Wih + 2048, p_b1, nullptr, nullptr, p_base1,
        4096, 2048, 2048, 4096, 4096, -1);

    // 12: econ = embg @ Wih[:,0:1024].T  (2688 x 4096, K=1024)
    gemm128<0><<<dim3(4096 / 128, (TTS * BBS) / 128), 256>>>(
        p_embg, l1Wih, nullptr, p_econ, 4096, 1024, 1024, 4096, 4096);

    // 13: zero states
    zero_states_kernel<<<(BBS * 4096) / 256, 256>>>();

    // 14: sequential decode (blocks/rows past the active prefix exit early)
    for (int t = 0; t < TTS; ++t) {
        gemm32<1><<<dim3(4096 / 128, 4), 128>>>(
            p_x1, p_W1, nullptr, p_base1, p_econ + (size_t)t * BBS * 4096,
            p_gates, 4096, 2048, 2048, 2048, 4096, t);

        lstm1_kernel<<<(BBS * DHID) / 256, 256>>>(t);

        gemm32<0><<<dim3(3072 / 128, 4), 128>>>(
            p_x2 + 2048, p_W3, p_b3, nullptr, nullptr, p_ag,
            3072, 1024, 4096, 1024, 3072, t);

        attn_kernel<<<BBS, 256>>>(faW, fab, t);

        gemm32<0><<<dim3(4096 / 128, 4), 128>>>(
            p_x2, p_W2, p_b2, nullptr, nullptr, p_gates,
            4096, 4096, 4096, 4096, 4096, t);

        lstm2_kernel<<<(BBS * DHID) / 256, 256>>>(t);
    }

    // 15: predictions = h2all[active] @ ram_W.T + ram_b (compact, scattered)
    gemm128<2><<<dim3(VOC / 128, (TTS * BBS + 127) / 128), 256>>>(
        p_h2, ramW, ramb, out + O_PRED, VOC, 1024, 1024, 1024, VOC);

    // 16: predicted_pos
    rpm_kernel<<<(TTS * BBS + 7) / 8, 256>>>(rpmW, out);
}

// round 8
// speedup vs baseline: 1.6011x; 1.1328x over previous
#include <cuda_runtime.h>
#include <math.h>

// ---------------------------------------------------------------------------
// Problem constants
// ---------------------------------------------------------------------------
#define TTS   21      // Tm = CAP-1 decode steps
#define CAPL  22
#define BBS   128     // batch
#define PPS   196     // pixels
#define ENCD  2048
#define DHID  1024
#define VOC   32000

static constexpr long long O_PRED = 0;
static constexpr long long O_CAPS = (long long)BBS * TTS * VOC;   // 86,016,000
static constexpr long long O_DECL = O_CAPS + (long long)BBS * CAPL;
static constexpr long long O_SORT = O_DECL + BBS;
static constexpr long long O_RPOS = O_SORT + BBS;
static constexpr long long O_PPOS = O_RPOS + (long long)BBS * TTS;

// ---------------------------------------------------------------------------
// Static device scratch (no runtime allocation allowed)
// ---------------------------------------------------------------------------
__device__ float d_encs [(size_t)BBS * PPS * ENCD];   // sorted encoder
__device__ float d_att1 [(size_t)BBS * PPS * DHID];   // att1
__device__ float d_econ [(size_t)TTS * BBS * 4 * DHID]; // embed @ Wih_e^T
__device__ float d_embg [(size_t)TTS * BBS * DHID];   // gathered embeddings
__device__ float d_W1cat[4096 * 2048];                // [Wih(:,1024:2048) | Whh]
__device__ float d_W2cat[(size_t)4096 * 4096];        // [l2_Wih | l2_Whh]
__device__ float d_W3cat[3072 * 1024];                // [dec_att_W ; f_beta_W]
__device__ float d_b1sum[4096];
__device__ float d_b2sum[4096];
__device__ float d_b3cat[3072];
__device__ float d_base1[BBS * 4096];                 // biases + mean_enc contrib
__device__ float d_gates[BBS * 4096];
__device__ float d_x1   [BBS * 2048];                 // [h2_state | h1_state]
__device__ float d_x2   [BBS * 4096];                 // [att | h1n | h2_state]
__device__ float d_ag   [BBS * 3072];                 // [att2 | gate logits]
__device__ float d_c1   [BBS * DHID];
__device__ float d_c2   [BBS * DHID];
__device__ float d_mean [BBS * ENCD];
__device__ float d_h2all[(size_t)TTS * BBS * DHID];   // h2n (active rows only)
__device__ int   d_sort  [BBS];
__device__ int   d_declen[BBS];
__device__ int   d_tokens[TTS * BBS];
__device__ int   d_nact  [TTS];                       // active prefix size per t
__device__ int   d_rowidx[TTS * BBS];                 // compact -> t*BBS+b
__device__ int   d_outrow[TTS * BBS];                 // compact -> b*TTS+t
__device__ int   d_cnt;                               // number of active pairs

// ---------------------------------------------------------------------------
// Math helpers
// ---------------------------------------------------------------------------
__device__ __forceinline__ float sigf(float x) {
    return 1.0f / (1.0f + __expf(-x));
}
__device__ __forceinline__ float tanh_fast(float x) {
    return 1.0f - 2.0f / (__expf(2.0f * x) + 1.0f);
}

// ---------------------------------------------------------------------------
// Setup: stable descending argsort; caps/dec_len/sort/rel_pos out; active
// prefix sizes and compact active-row lists.
// ---------------------------------------------------------------------------
__global__ void setup_kernel(const int* __restrict__ caplen,
                             const int* __restrict__ caps,
                             float* __restrict__ out) {
    __shared__ int lens_s[BBS];
    __shared__ int sort_s[BBS];
    __shared__ int dl_s[BBS];
    int i = threadIdx.x;
    int li = caplen[i];
    lens_s[i] = li;
    __syncthreads();
    int rank = 0;
    for (int j = 0; j < BBS; ++j) {
        int lj = lens_s[j];
        if (lj > li || (lj == li && j < i)) rank++;
    }
    sort_s[rank] = i;
    __syncthreads();
    int src = sort_s[i];
    d_sort[i] = src;
    int dl = lens_s[src] - 1;
    d_declen[i] = dl;
    dl_s[i] = dl;
    out[O_DECL + i] = (float)dl;
    out[O_SORT + i] = (float)src;
    for (int t = 0; t < CAPL; ++t) {
        int tok = caps[src * CAPL + t];
        out[O_CAPS + (long long)i * CAPL + t] = (float)tok;
        if (t < TTS) d_tokens[t * BBS + i] = tok;
    }
    float dlf = (float)dl;
    for (int s = 0; s < TTS; ++s)
        out[O_RPOS + (long long)i * TTS + s] =
            (s < dl) ? ((float)(s + 1) / dlf) : 0.0f;
    __syncthreads();
    if (i == 0) {
        int c = 0;
        for (int t = 0; t < TTS; ++t) {
            int n = 0;
            while (n < BBS && dl_s[n] > t) n++;   // dl_s sorted descending
            d_nact[t] = n;
            for (int b = 0; b < n; ++b) {
                d_rowidx[c] = t * BBS + b;
                d_outrow[c] = b * TTS + t;
                c++;
            }
        }
        d_cnt = c;
    }
}

// ---------------------------------------------------------------------------
// Gather sorted encoder rows (float4)
// ---------------------------------------------------------------------------
__global__ void gather_enc_kernel(const float* __restrict__ enc) {
    int g = blockIdx.x * 256 + threadIdx.x;
    const int V4ROW = ENCD / 4;                      // 512
    int r = g / V4ROW;
    int w = g % V4ROW;
    int b = r / PPS, p = r % PPS;
    int srow = d_sort[b] * PPS + p;
    const float4* src = (const float4*)enc;
    float4* dst = (float4*)d_encs;
    dst[(size_t)r * V4ROW + w] = src[(size_t)srow * V4ROW + w];
}

// ---------------------------------------------------------------------------
// mean over pixels: one thread per (b,e)
// ---------------------------------------------------------------------------
__global__ void mean_kernel() {
    int idx = blockIdx.x * 256 + threadIdx.x;
    int b = idx / ENCD, e = idx % ENCD;
    const float* base = d_encs + (size_t)b * PPS * ENCD + e;
    float s = 0.f;
    #pragma unroll 4
    for (int p = 0; p < PPS; ++p) s += base[(size_t)p * ENCD];
    d_mean[idx] = s * (1.0f / (float)PPS);
}

// ---------------------------------------------------------------------------
// Weight concatenation copies (float4) + bias sums
// ---------------------------------------------------------------------------
__global__ void w1copy_kernel(const float* __restrict__ l1Wih,
                              const float* __restrict__ l1Whh) {
    int g = blockIdx.x * 256 + threadIdx.x;
    int j = g / (2048 / 4);
    int c = (g % (2048 / 4)) * 4;
    float4 v;
    if (c < 1024) v = *(const float4*)(l1Wih + (size_t)j * 4096 + 1024 + c);
    else          v = *(const float4*)(l1Whh + (size_t)j * 1024 + (c - 1024));
    *(float4*)(d_W1cat + (size_t)j * 2048 + c) = v;
}

__global__ void w2copy_kernel(const float* __restrict__ l2Wih,
                              const float* __restrict__ l2Whh) {
    int g = blockIdx.x * 256 + threadIdx.x;
    int j = g / (4096 / 4);
    int c = (g % (4096 / 4)) * 4;
    float4 v;
    if (c < 3072) v = *(const float4*)(l2Wih + (size_t)j * 3072 + c);
    else          v = *(const float4*)(l2Whh + (size_t)j * 1024 + (c - 3072));
    *(float4*)(d_W2cat + (size_t)j * 4096 + c) = v;
}

__global__ void w3copy_kernel(const float* __restrict__ daW,
                              const float* __restrict__ fbW) {
    int g = blockIdx.x * 256 + threadIdx.x;
    int j = g / (1024 / 4);
    int c = (g % (1024 / 4)) * 4;
    float4 v;
    if (j < 1024) v = *(const float4*)(daW + (size_t)j * 1024 + c);
    else          v = *(const float4*)(fbW + (size_t)(j - 1024) * 1024 + c);
    *(float4*)(d_W3cat + (size_t)j * 1024 + c) = v;
}

__global__ void bias_kernel(const float* __restrict__ l1bih,
                            const float* __restrict__ l1bhh,
                            const float* __restrict__ l2bih,
                            const float* __restrict__ l2bhh,
                            const float* __restrict__ dab,
                            const float* __restrict__ fbb) {
    int j = blockIdx.x * 256 + threadIdx.x;
    d_b1sum[j] = l1bih[j] + l1bhh[j];
    d_b2sum[j] = l2bih[j] + l2bhh[j];
    if (j < 3072) d_b3cat[j] = (j < 1024) ? dab[j] : fbb[j - 1024];
}

// ---------------------------------------------------------------------------
// Gather token embeddings: one block per (t,b) row
// ---------------------------------------------------------------------------
__global__ void embg_kernel(const float* __restrict__ emb) {
    int m = blockIdx.x;
    int tok = d_tokens[m];
    const float4* src = (const float4*)(emb + (size_t)tok * DHID);
    float4* dst = (float4*)(d_embg + (size_t)m * DHID);
    dst[threadIdx.x] = src[threadIdx.x];
}

// ---------------------------------------------------------------------------
// Zero initial states / zero the whole predictions region
// ---------------------------------------------------------------------------
__global__ void zero_states_kernel() {
    int idx = blockIdx.x * 256 + threadIdx.x;        // 0 .. 524287
    d_x2[idx] = 0.f;
    if (idx < BBS * 2048) d_x1[idx] = 0.f;
    if (idx < BBS * DHID) { d_c1[idx] = 0.f; d_c2[idx] = 0.f; }
}

__global__ void zero_pred_kernel(float* __restrict__ out) {
    size_t g = (size_t)blockIdx.x * 256 + threadIdx.x;  // float4 index
    ((float4*)out)[g] = make_float4(0.f, 0.f, 0.f, 0.f);
}

// ---------------------------------------------------------------------------
// Big GEMM: 128x128 tile, BK=16, 256 threads, 8x8 microtile with 4+4 split
// fragments (conflict-free LDS.128), register-prefetch pipelining. fp32.
// C[m,n] = sum_k A[m,k]*B[n,k]
// MODE 0: plain   MODE 1: +bias[n]
// MODE 2: +bias, A-rows gathered via d_rowidx, stores scattered via d_outrow,
//         rows >= d_cnt skipped (predictions path).
// ---------------------------------------------------------------------------
template<int MODE>
__global__ void __launch_bounds__(256, 2)
gemm128(const float* __restrict__ A,
        const float* __restrict__ Bm,
        const float* __restrict__ bias,
        float* __restrict__ C,
        int N, int K, int lda, int ldb, int ldc) {
    __shared__ float As[16][132];
    __shared__ float Bs[16][132];
    const int tid = threadIdx.x;
    const int m0 = blockIdx.y * 128;
    const int n0 = blockIdx.x * 128;
    int count = 0;
    if (MODE == 2) {
        count = d_cnt;
        if (m0 >= count) return;
    }
    const int lr = tid >> 1;            // load row 0..127
    const int lc = (tid & 1) * 8;       // col base 0 or 8
    int arow = m0 + lr;
    if (MODE == 2) arow = (m0 + lr < count) ? d_rowidx[m0 + lr] : d_rowidx[0];
    const float* Aptr = A + (size_t)arow * lda + lc;
    const float* Bptr = Bm + (size_t)(n0 + lr) * ldb + lc;

    const int ty = tid >> 4;            // 0..15 (m)
    const int tx = tid & 15;            // 0..15 (n)

    float acc[8][8];
    #pragma unroll
    for (int i = 0; i < 8; ++i)
        #pragma unroll
        for (int j = 0; j < 8; ++j) acc[i][j] = 0.f;

    // prefetch first K-tile into registers
    float4 pa0 = *(const float4*)(Aptr);
    float4 pa1 = *(const float4*)(Aptr + 4);
    float4 pb0 = *(const float4*)(Bptr);
    float4 pb1 = *(const float4*)(Bptr + 4);

    for (int k0 = 0; k0 < K; k0 += 16) {
        As[lc + 0][lr] = pa0.x; As[lc + 1][lr] = pa0.y;
        As[lc + 2][lr] = pa0.z; As[lc + 3][lr] = pa0.w;
        As[lc + 4][lr] = pa1.x; As[lc + 5][lr] = pa1.y;
        As[lc + 6][lr] = pa1.z; As[lc + 7][lr] = pa1.w;
        Bs[lc + 0][lr] = pb0.x; Bs[lc + 1][lr] = pb0.y;
        Bs[lc + 2][lr] = pb0.z; Bs[lc + 3][lr] = pb0.w;
        Bs[lc + 4][lr] = pb1.x; Bs[lc + 5][lr] = pb1.y;
        Bs[lc + 6][lr] = pb1.z; Bs[lc + 7][lr] = pb1.w;
        __syncthreads();
        if (k0 + 16 < K) {                           // prefetch next tile
            pa0 = *(const float4*)(Aptr + k0 + 16);
            pa1 = *(const float4*)(Aptr + k0 + 20);
            pb0 = *(const float4*)(Bptr + k0 + 16);
            pb1 = *(const float4*)(Bptr + k0 + 20);
        }
        #pragma unroll
        for (int kk = 0; kk < 16; ++kk) {
            float a[8], b[8];
            *(float4*)(a)     = *(const float4*)&As[kk][ty * 4];
            *(float4*)(a + 4) = *(const float4*)&As[kk][64 + ty * 4];
            *(float4*)(b)     = *(const float4*)&Bs[kk][tx * 4];
            *(float4*)(b + 4) = *(const float4*)&Bs[kk][64 + tx * 4];
            #pragma unroll
            for (int i = 0; i < 8; ++i)
                #pragma unroll
                for (int j = 0; j < 8; ++j)
                    acc[i][j] = fmaf(a[i], b[j], acc[i][j]);
        }
        __syncthreads();
    }

    float bv[8];
    #pragma unroll
    for (int j = 0; j < 8; ++j) {
        int n = (j < 4) ? (n0 + tx * 4 + j) : (n0 + 64 + tx * 4 + j - 4);
        bv[j] = (MODE >= 1) ? bias[n] : 0.f;
    }

    #pragma unroll
    for (int i = 0; i < 8; ++i) {
        int mi = (i < 4) ? (ty * 4 + i) : (64 + ty * 4 + i - 4);
        int m = m0 + mi;
        long long crow = m;
        if (MODE == 2) {
            if (m >= count) continue;
            crow = d_outrow[m];
        }
        float* dst = C + crow * (long long)ldc + n0;
        float4 v0, v1;
        v0.x = acc[i][0] + bv[0]; v0.y = acc[i][1] + bv[1];
        v0.z = acc[i][2] + bv[2]; v0.w = acc[i][3] + bv[3];
        v1.x = acc[i][4] + bv[4]; v1.y = acc[i][5] + bv[5];
        v1.z = acc[i][6] + bv[6]; v1.w = acc[i][7] + bv[7];
        *(float4*)(dst + tx * 4)      = v0;
        *(float4*)(dst + 64 + tx * 4) = v1;
    }
}

// ---------------------------------------------------------------------------
// Skinny GEMM: 32x128 tile, BK=16, 128 threads, 4x8 microtile with 4+4 split
// n-fragments (conflict-free LDS.128), register prefetch. fp32.
// MODE 0: +bias[n]    MODE 1: +add0[m,n] + add1[m,n]  (stride ldc)
// t >= 0: early-exit blocks whose rows are entirely inactive (m0 >= nact[t]).
// ---------------------------------------------------------------------------
template<int MODE>
__global__ void __launch_bounds__(128)
gemm32(const float* __restrict__ A,
       const float* __restrict__ Bm,
       const float* __restrict__ bias,
       const float* __restrict__ add0,
       const float* __restrict__ add1,
       float* __restrict__ C,
       int N, int K, int lda, int ldb, int ldc, int t) {
    const int m0 = blockIdx.y * 32;
    if (t >= 0 && m0 >= d_nact[t]) return;
    __shared__ float As[16][36];
    __shared__ float Bs[16][132];
    const int tid = threadIdx.x;
    const int n0 = blockIdx.x * 128;

    const int ar = tid >> 2;            // A load row 0..31
    const int ac = (tid & 3) * 4;       // A col 0,4,8,12
    const float* Aptr = A + (size_t)(m0 + ar) * lda + ac;
    const float* Bptr = Bm + (size_t)(n0 + tid) * ldb;

    const int ty = tid >> 4;            // 0..7  (m)
    const int tx = tid & 15;            // 0..15 (n)

    float acc[4][8];
    #pragma unroll
    for (int i = 0; i < 4; ++i)
        #pragma unroll
        for (int j = 0; j < 8; ++j) acc[i][j] = 0.f;

    float4 pav = *(const float4*)(Aptr);
    float4 pb[4];
    #pragma unroll
    for (int j = 0; j < 4; ++j) pb[j] = *(const float4*)(Bptr + j * 4);

    for (int k0 = 0; k0 < K; k0 += 16) {
        As[ac + 0][ar] = pav.x; As[ac + 1][ar] = pav.y;
        As[ac + 2][ar] = pav.z; As[ac + 3][ar] = pav.w;
        #pragma unroll
        for (int j = 0; j < 4; ++j) {
            Bs[j * 4 + 0][tid] = pb[j].x; Bs[j * 4 + 1][tid] = pb[j].y;
            Bs[j * 4 + 2][tid] = pb[j].z; Bs[j * 4 + 3][tid] = pb[j].w;
        }
        __syncthreads();
        if (k0 + 16 < K) {
            pav = *(const float4*)(Aptr + k0 + 16);
            #pragma unroll
            for (int j = 0; j < 4; ++j)
                pb[j] = *(const float4*)(Bptr + k0 + 16 + j * 4);
        }
        #pragma unroll
        for (int kk = 0; kk < 16; ++kk) {
            float a[4], b[8];
            *(float4*)(a)     = *(const float4*)&As[kk][ty * 4];
            *(float4*)(b)     = *(const float4*)&Bs[kk][tx * 4];
            *(float4*)(b + 4) = *(const float4*)&Bs[kk][64 + tx * 4];
            #pragma unroll
            for (int i = 0; i < 4; ++i)
                #pragma unroll
                for (int j = 0; j < 8; ++j)
                    acc[i][j] = fmaf(a[i], b[j], acc[i][j]);
        }
        __syncthreads();
    }

    float bv[8];
    #pragma unroll
    for (int j = 0; j < 8; ++j) {
        int n = (j < 4) ? (n0 + tx * 4 + j) : (n0 + 64 + tx * 4 + j - 4);
        bv[j] = (MODE == 0) ? bias[n] : 0.f;
    }

    #pragma unroll
    for (int i = 0; i < 4; ++i) {
        int m = m0 + ty * 4 + i;
        float* dst = C + (size_t)m * ldc + n0;
        float add[8];
        if (MODE == 1) {
            const float* a0p = add0 + (size_t)m * ldc + n0;
            const float* a1p = add1 + (size_t)m * ldc + n0;
            #pragma unroll
            for (int j = 0; j < 4; ++j) {
                add[j]     = a0p[tx * 4 + j]      + a1p[tx * 4 + j];
                add[j + 4] = a0p[64 + tx * 4 + j] + a1p[64 + tx * 4 + j];
            }
        } else {
            #pragma unroll
            for (int j = 0; j < 8; ++j) add[j] = bv[j];
        }
        float4 v0, v1;
        v0.x = acc[i][0] + add[0]; v0.y = acc[i][1] + add[1];
        v0.z = acc[i][2] + add[2]; v0.w = acc[i][3] + add[3];
        v1.x = acc[i][4] + add[4]; v1.y = acc[i][5] + add[5];
        v1.z = acc[i][6] + add[6]; v1.w = acc[i][7] + add[7];
        *(float4*)(dst + tx * 4)      = v0;
        *(float4*)(dst + 64 + tx * 4) = v1;
    }
}

// ---------------------------------------------------------------------------
// LSTM pointwise kernels (gate order: i, f, g, o). Inactive rows skipped.
// ---------------------------------------------------------------------------
__global__ void lstm1_kernel(int t) {
    int idx = blockIdx.x * 256 + threadIdx.x;
    int b = idx / DHID, k = idx % DHID;
    if (t >= d_declen[b]) return;
    const float* g = d_gates + (size_t)b * 4096;
    float ig = g[k], fg = g[1024 + k], gg = g[2048 + k], og = g[3072 + k];
    float c = d_c1[idx];
    float cn = sigf(fg) * c + sigf(ig) * tanhf(gg);
    float hn = sigf(og) * tanhf(cn);
    d_c1[idx] = cn;
    d_x1[(size_t)b * 2048 + 1024 + k] = hn;          // carried h1 state
    d_x2[(size_t)b * 4096 + 2048 + k] = hn;          // h1n for att2/gates2
}

__global__ void lstm2_kernel(int t) {
    int idx = blockIdx.x * 256 + threadIdx.x;
    int b = idx / DHID, k = idx % DHID;
    if (t >= d_declen[b]) return;
    const float* g = d_gates + (size_t)b * 4096;
    float ig = g[k], fg = g[1024 + k], gg = g[2048 + k], og = g[3072 + k];
    float c = d_c2[idx];
    float cn = sigf(fg) * c + sigf(ig) * tanhf(gg);
    float hn = sigf(og) * tanhf(cn);
    d_c2[idx] = cn;
    d_h2all[(size_t)(t * BBS + b) * DHID + k] = hn;
    d_x1[(size_t)b * 2048 + k] = hn;                 // carried h2 state
    d_x2[(size_t)b * 4096 + 3072 + k] = hn;
}

// ---------------------------------------------------------------------------
// Fused attention: scores = tanh(att1 + att2) . w + b0; softmax over p;
// awe = alpha @ enc; x2.att = sigmoid(gate_logits) * awe.  One block per b.
// ---------------------------------------------------------------------------
__global__ void attn_kernel(const float* __restrict__ fullW,
                            const float* __restrict__ fullb, int t) {
    const int b = blockIdx.x;
    if (t >= d_declen[b]) return;
    __shared__ float s_a2[DHID];
    __shared__ float s_w [DHID];
    __shared__ float s_sc[PPS];
    __shared__ float s_red[256];
    const int tid = threadIdx.x;
    const int lane = tid & 31, warp = tid >> 5;

    for (int i = tid; i < DHID; i += 256) {
        s_a2[i] = d_ag[(size_t)b * 3072 + i];
        s_w[i]  = fullW[i];
    }
    __syncthreads();

    const float b0 = fullb[0];
    for (int p = warp; p < PPS; p += 8) {
        const float* row = d_att1 + ((size_t)b * PPS + p) * DHID;
        float s = 0.f;
        #pragma unroll 8
        for (int a = lane; a < DHID; a += 32)
            s += tanh_fast(row[a] + s_a2[a]) * s_w[a];
        #pragma unroll
        for (int o = 16; o > 0; o >>= 1)
            s += __shfl_down_sync(0xffffffffu, s, o);
        if (lane == 0) s_sc[p] = s + b0;
    }
    __syncthreads();

    s_red[tid] = (tid < PPS) ? s_sc[tid] : -INFINITY;
    __syncthreads();
    for (int s = 128; s > 0; s >>= 1) {
        if (tid < s) s_red[tid] = fmaxf(s_red[tid], s_red[tid + s]);
        __syncthreads();
    }
    float mx = s_red[0];
    __syncthreads();
    float e = 0.f;
    if (tid < PPS) e = __expf(s_sc[tid] - mx);
    s_red[tid] = e;
    __syncthreads();
    for (int s = 128; s > 0; s >>= 1) {
        if (tid < s) s_red[tid] += s_red[tid + s];
        __syncthreads();
    }
    float inv = 1.0f / s_red[0];
    __syncthreads();
    if (tid < PPS) s_sc[tid] = e * inv;
    __syncthreads();

    const float* encb = d_encs + (size_t)b * PPS * ENCD;
    for (int ei = tid; ei < ENCD; ei += 256) {
        float acc = 0.f;
        const float* col = encb + ei;
        #pragma unroll 4
        for (int p = 0; p < PPS; ++p)
            acc = fmaf(s_sc[p], col[(size_t)p * ENCD], acc);
        float gate = sigf(d_ag[(size_t)b * 3072 + 1024 + ei]);
        d_x2[(size_t)b * 4096 + ei] = gate * acc;
    }
}

// ---------------------------------------------------------------------------
// predicted_pos: one warp per (t,b) row
// ---------------------------------------------------------------------------
__global__ void rpm_kernel(const float* __restrict__ rpmW,
                           float* __restrict__ out) {
    int m = blockIdx.x * 8 + (threadIdx.x >> 5);
    if (m >= TTS * BBS) return;
    int lane = threadIdx.x & 31;
    int t = m / BBS, b = m % BBS;
    const float* h = d_h2all + (size_t)m * DHID;
    float s = 0.f;
    #pragma unroll 8
    for (int k = lane; k < DHID; k += 32) s += h[k] * rpmW[k];
    #pragma unroll
    for (int o = 16; o > 0; o >>= 1)
        s += __shfl_down_sync(0xffffffffu, s, o);
    if (lane == 0)
        out[O_PPOS + (long long)b * TTS + t] =
            (t < d_declen[b]) ? sigf(s) : 0.f;
}

// ---------------------------------------------------------------------------
// Launch
// ---------------------------------------------------------------------------
extern "C" void kernel_launch(void* const* d_in, const int* in_sizes, int n_in,
                              void* d_out, int out_size) {
    const float* enc_out = (const float*)d_in[0];
    const int*   caps    = (const int*)  d_in[1];
    const int*   caplen  = (const int*)  d_in[2];
    const float* emb     = (const float*)d_in[3];
    const float* eaW     = (const float*)d_in[4];
    const float* eab     = (const float*)d_in[5];
    const float* daW     = (const float*)d_in[6];
    const float* dab     = (const float*)d_in[7];
    const float* faW     = (const float*)d_in[8];
    const float* fab     = (const float*)d_in[9];
    const float* fbW     = (const float*)d_in[10];
    const float* fbb     = (const float*)d_in[11];
    const float* l1Wih   = (const float*)d_in[12];
    const float* l1Whh   = (const float*)d_in[13];
    const float* l1bih   = (const float*)d_in[14];
    const float* l1bhh   = (const float*)d_in[15];
    const float* l2Wih   = (const float*)d_in[16];
    const float* l2Whh   = (const float*)d_in[17];
    const float* l2bih   = (const float*)d_in[18];
    const float* l2bhh   = (const float*)d_in[19];
    const float* ramW    = (const float*)d_in[20];
    const float* ramb    = (const float*)d_in[21];
    const float* rpmW    = (const float*)d_in[22];
    float* out = (float*)d_out;

    float* p_encs;  cudaGetSymbolAddress((void**)&p_encs,  d_encs);
    float* p_att1;  cudaGetSymbolAddress((void**)&p_att1,  d_att1);
    float* p_econ;  cudaGetSymbolAddress((void**)&p_econ,  d_econ);
    float* p_embg;  cudaGetSymbolAddress((void**)&p_embg,  d_embg);
    float* p_W1;    cudaGetSymbolAddress((void**)&p_W1,    d_W1cat);
    float* p_W2;    cudaGetSymbolAddress((void**)&p_W2,    d_W2cat);
    float* p_W3;    cudaGetSymbolAddress((void**)&p_W3,    d_W3cat);
    float* p_b1;    cudaGetSymbolAddress((void**)&p_b1,    d_b1sum);
    float* p_b2;    cudaGetSymbolAddress((void**)&p_b2,    d_b2sum);
    float* p_b3;    cudaGetSymbolAddress((void**)&p_b3,    d_b3cat);
    float* p_base1; cudaGetSymbolAddress((void**)&p_base1, d_base1);
    float* p_gates; cudaGetSymbolAddress((void**)&p_gates, d_gates);
    float* p_x1;    cudaGetSymbolAddress((void**)&p_x1,    d_x1);
    float* p_x2;    cudaGetSymbolAddress((void**)&p_x2,    d_x2);
    float* p_ag;    cudaGetSymbolAddress((void**)&p_ag,    d_ag);
    float* p_mean;  cudaGetSymbolAddress((void**)&p_mean,  d_mean);
    float* p_h2;    cudaGetSymbolAddress((void**)&p_h2,    d_h2all);

    // 1-3: sort, gather encoder, mean
    setup_kernel<<<1, BBS>>>(caplen, caps, out);
    gather_enc_kernel<<<50176, 256>>>(enc_out);
    mean_kernel<<<(BBS * ENCD) / 256, 256>>>();

    // 4: att1 = enc_sorted @ enc_att_W.T + b  (25088 x 1024, K=2048)
    //    (kept in the ncu-profiled launch slot for a clean A/B)
    gemm128<1><<<dim3(1024 / 128, (BBS * PPS) / 128), 256>>>(
        p_encs, eaW, eab, p_att1, 1024, 2048, 2048, 2048, 1024);

    // 5: zero whole predictions region (inactive rows stay 0)
    zero_pred_kernel<<<84000, 256>>>(out + O_PRED);

    // 6-9: bias sums + weight concatenations
    bias_kernel<<<16, 256>>>(l1bih, l1bhh, l2bih, l2bhh, dab, fbb);
    w1copy_kernel<<<8192, 256>>>(l1Wih, l1Whh);
    w2copy_kernel<<<16384, 256>>>(l2Wih, l2Whh);
    w3copy_kernel<<<3072, 256>>>(daW, fbW);

    // 10: token embedding gather
    embg_kernel<<<TTS * BBS, 256>>>(emb);

    // 11: base1 = mean_enc @ Wih[:,2048:].T + (bih+bhh)  (128 x 4096, K=2048)
    gemm32<0><<<dim3(4096 / 128, 4), 128>>>(
        p_mean, l1Wih + 2048, p_b1, nullptr, nullptr, p_base1,
        4096, 2048, 2048, 4096, 4096, -1);

    // 12: econ = embg @ Wih[:,0:1024].T  (2688 x 4096, K=1024)
    gemm128<0><<<dim3(4096 / 128, (TTS * BBS) / 128), 256>>>(
        p_embg, l1Wih, nullptr, p_econ, 4096, 1024, 1024, 4096, 4096);

    // 13: zero states
    zero_states_kernel<<<(BBS * 4096) / 256, 256>>>();

    // 14: sequential decode (blocks/rows past the active prefix exit early)
    for (int t = 0; t < TTS; ++t) {
        gemm32<1><<<dim3(4096 / 128, 4), 128>>>(
            p_x1, p_W1, nullptr, p_base1, p_econ + (size_t)t * BBS * 4096,
            p_gates, 4096, 2048, 2048, 2048, 4096, t);

        lstm1_kernel<<<(BBS * DHID) / 256, 256>>>(t);

        gemm32<0><<<dim3(3072 / 128, 4), 128>>>(
            p_x2 + 2048, p_W3, p_b3, nullptr, nullptr, p_ag,
            3072, 1024, 4096, 1024, 3072, t);

        attn_kernel<<<BBS, 256>>>(faW, fab, t);

        gemm32<0><<<dim3(4096 / 128, 4), 128>>>(
            p_x2, p_W2, p_b2, nullptr, nullptr, p_gates,
            4096, 4096, 4096, 4096, 4096, t);

        lstm2_kernel<<<(BBS * DHID) / 256, 256>>>(t);
    }

    // 15: predictions = h2all[active] @ ram_W.T + ram_b (compact, scattered)
    gemm128<2><<<dim3(VOC / 128, (TTS * BBS + 127) / 128), 256>>>(
        p_h2, ramW, ramb, out + O_PRED, VOC, 1024, 1024, 1024, VOC);

    // 16: predicted_pos
    rpm_kernel<<<(TTS * BBS + 7) / 8, 256>>>(rpmW, out);
}